// round 1
// baseline (speedup 1.0000x reference)
#include <cuda_runtime.h>
#include <math.h>
#include <stdint.h>

// Problem constants (fixed by the dataset)
#define NN   50000
#define NE   600000
#define NG   128
#define CIN  128
#define PROJ 128
#define MM   384          // OUT_CH * K
#define M3   1152         // 3 * MM
#define EPSV 1e-5f

// ---------------- scratch (static device globals; no allocation allowed) ---
__device__ float g_neigh[(size_t)NN * CIN];     // 25.6 MB
__device__ float g_Hc[(size_t)NN * MM];         // 76.8 MB  [X | H1 | H2]
__device__ float g_Hm[(size_t)NN * MM];         // 76.8 MB  pre-BN hidden
__device__ float g_Hadd[NG * MM];
__device__ float g_Hmax[NG * MM];
__device__ float g_cnt[NG];
__device__ float g_sum0[PROJ], g_ssq0[PROJ], g_scale0[PROJ], g_shift0[PROJ];
__device__ float g_sumH[MM],  g_ssqH[MM],  g_scaleH[MM],  g_shiftH[MM];
__device__ float g_h0[NG * M3];
__device__ float g_h1[NG * 768];
__device__ float g_h2[NG * MM];

// ---------------- helpers ---------------------------------------------------
__device__ __forceinline__ void atomicMaxF(float* addr, float v) {
    // monotone int/uint trick (valid incl. -inf init; no NaNs expected)
    if (v >= 0.f) atomicMax((int*)addr, __float_as_int(v));
    else          atomicMin((unsigned int*)addr, (unsigned int)__float_as_int(v));
}

// ---------------- generic fill ----------------------------------------------
__global__ void fill_f(float* p, size_t n, float v) {
    size_t i  = (size_t)blockIdx.x * blockDim.x + threadIdx.x;
    size_t st = (size_t)gridDim.x * blockDim.x;
    for (; i < n; i += st) p[i] = v;
}

// ---------------- edge scatter-add: dst[didx[e]] += src[sidx[e]] (128 ch) ---
__global__ void scatter_add(const float* __restrict__ src, int lds,
                            float* dst, int ldd,
                            const int* __restrict__ sidx,
                            const int* __restrict__ didx, int E) {
    int e = blockIdx.x * blockDim.y + threadIdx.y;
    if (e >= E) return;
    int s = sidx[e];
    int d = didx[e];
    const float4* sp = (const float4*)(src + (size_t)s * lds);
    float4 v = sp[threadIdx.x];                 // 32 lanes x float4 = 128 ch
    float* dp = dst + (size_t)d * ldd + threadIdx.x * 4;
    atomicAdd(dp + 0, v.x);
    atomicAdd(dp + 1, v.y);
    atomicAdd(dp + 2, v.z);
    atomicAdd(dp + 3, v.w);
}

// ---------------- SIMT sgemm: C[N,128] = A[N,K] @ W[128,K]^T (+bias / +=) ---
// BM=BN=128, BK=8, 256 threads, 8x8 microtile. One call covers exactly 128
// output channels (W pointer pre-offset by caller).
__global__ void __launch_bounds__(256)
sgemm_tn(const float* __restrict__ A, int lda,
         const float* __restrict__ W, int ldw,
         const float* __restrict__ bias,
         float* __restrict__ C, int ldc,
         int N, int K, int accumulate) {
    __shared__ float As[8][128];
    __shared__ float Bs[8][128];
    const int tid  = threadIdx.x;
    const int row0 = blockIdx.x * 128;
    const int lr   = tid >> 1;        // 0..127
    const int lk   = (tid & 1) * 4;   // 0 or 4
    const int tx   = tid & 15;        // 0..15
    const int ty   = tid >> 4;        // 0..15

    float acc[8][8];
#pragma unroll
    for (int i = 0; i < 8; i++)
#pragma unroll
        for (int j = 0; j < 8; j++) acc[i][j] = 0.f;

    for (int k0 = 0; k0 < K; k0 += 8) {
        float4 av = make_float4(0.f, 0.f, 0.f, 0.f);
        int ar = row0 + lr;
        if (ar < N) av = *(const float4*)(A + (size_t)ar * lda + k0 + lk);
        As[lk + 0][lr] = av.x; As[lk + 1][lr] = av.y;
        As[lk + 2][lr] = av.z; As[lk + 3][lr] = av.w;

        float4 wv = *(const float4*)(W + (size_t)lr * ldw + k0 + lk);
        Bs[lk + 0][lr] = wv.x; Bs[lk + 1][lr] = wv.y;
        Bs[lk + 2][lr] = wv.z; Bs[lk + 3][lr] = wv.w;
        __syncthreads();

#pragma unroll
        for (int k = 0; k < 8; k++) {
            float ra[8], rb[8];
#pragma unroll
            for (int i = 0; i < 8; i++) ra[i] = As[k][ty * 8 + i];
#pragma unroll
            for (int j = 0; j < 8; j++) rb[j] = Bs[k][tx * 8 + j];
#pragma unroll
            for (int i = 0; i < 8; i++)
#pragma unroll
                for (int j = 0; j < 8; j++) acc[i][j] = fmaf(ra[i], rb[j], acc[i][j]);
        }
        __syncthreads();
    }

#pragma unroll
    for (int i = 0; i < 8; i++) {
        int r = row0 + ty * 8 + i;
        if (r >= N) continue;
        float* crow = C + (size_t)r * ldc + tx * 8;
        if (accumulate) {
#pragma unroll
            for (int j = 0; j < 8; j++) crow[j] += acc[i][j];
        } else {
#pragma unroll
            for (int j = 0; j < 8; j++) {
                float b = bias ? bias[tx * 8 + j] : 0.f;
                crow[j] = acc[i][j] + b;
            }
        }
    }
}

// ---------------- column-wise sum / sumsq (BN stats over nodes) -------------
__global__ void colstats(const float* __restrict__ A, int lda, int N,
                         float* sum, float* ssq) {
    int c = threadIdx.x;                 // blockDim.x == #cols
    float s = 0.f, q = 0.f;
    for (int r = blockIdx.x; r < N; r += gridDim.x) {
        float v = A[(size_t)r * lda + c];
        s += v;
        q += v * v;
    }
    atomicAdd(&sum[c], s);
    atomicAdd(&ssq[c], q);
}

__global__ void mkaffine(const float* sum, const float* ssq,
                         const float* g, const float* b,
                         float* scale, float* shift, int C, float invN) {
    int c = blockIdx.x * blockDim.x + threadIdx.x;
    if (c >= C) return;
    float m  = sum[c] * invN;
    float v  = fmaxf(ssq[c] * invN - m * m, 0.f);
    float sc = g[c] * rsqrtf(v + EPSV);
    scale[c] = sc;
    shift[c] = b[c] - m * sc;
}

// ---------------- apply BN in place on 128-col slab of a 384-stride array ---
__global__ void applybn(float* A, int lda, int C, int N,
                        const float* __restrict__ scale,
                        const float* __restrict__ shift) {
    size_t total = (size_t)N * C;
    size_t i  = (size_t)blockIdx.x * blockDim.x + threadIdx.x;
    size_t st = (size_t)gridDim.x * blockDim.x;
    for (; i < total; i += st) {
        int r = (int)(i / C), c = (int)(i % C);
        float* p = A + (size_t)r * lda + c;
        *p = fmaf(*p, scale[c], shift[c]);
    }
}

// ---------------- fused BN-apply + segment add/max pooling ------------------
// batch is sorted -> accumulate locally, flush atomics only on graph change.
#define POOL_NPB 64
__global__ void __launch_bounds__(384)
pool_kernel(const float* __restrict__ Hm,
            const float* __restrict__ scale, const float* __restrict__ shift,
            const int* __restrict__ batch, int N,
            float* Hadd, float* Hmax, float* cnt) {
    __shared__ int sb[POOL_NPB];
    int c  = threadIdx.x;                 // 0..383
    int n0 = blockIdx.x * POOL_NPB;
    int nEnd = min(n0 + POOL_NPB, N);
    if (c < POOL_NPB && n0 + c < N) sb[c] = batch[n0 + c];
    __syncthreads();

    float sc = scale[c], sh = shift[c];
    float accA = 0.f, accM = -INFINITY, accC = 0.f;
    int curg = -1;
    for (int n = n0; n < nEnd; n++) {
        int g = sb[n - n0];
        if (g != curg) {
            if (curg >= 0) {
                atomicAdd(&Hadd[(size_t)curg * MM + c], accA);
                atomicMaxF(&Hmax[(size_t)curg * MM + c], accM);
                if (c == 0) atomicAdd(&cnt[curg], accC);
            }
            accA = 0.f; accM = -INFINITY; accC = 0.f; curg = g;
        }
        float v = fmaf(Hm[(size_t)n * MM + c], sc, sh);
        accA += v;
        accM = fmaxf(accM, v);
        accC += 1.f;
    }
    if (curg >= 0) {
        atomicAdd(&Hadd[(size_t)curg * MM + c], accA);
        atomicMaxF(&Hmax[(size_t)curg * MM + c], accM);
        if (c == 0) atomicAdd(&cnt[curg], accC);
    }
}

// ---------------- BN over graphs (128 rows) for the 1152-col concat ---------
__global__ void bn_graphs(const float* __restrict__ Hadd,
                          const float* __restrict__ Hmax,
                          const float* __restrict__ cnt,
                          const float* __restrict__ g,
                          const float* __restrict__ b,
                          float* __restrict__ h0) {
    int col = blockIdx.x;     // 0..1151
    int t   = threadIdx.x;    // 0..127 (graph)
    float v;
    if (col < MM) {
        v = Hadd[(size_t)t * MM + col] / fmaxf(cnt[t], 1.f);
    } else if (col < 2 * MM) {
        v = Hadd[(size_t)t * MM + (col - MM)];
    } else {
        v = Hmax[(size_t)t * MM + (col - 2 * MM)];
        if (!isfinite(v)) v = 0.f;   // empty-segment guard
    }
    __shared__ float s1[128], s2[128];
    s1[t] = v; s2[t] = v * v;
    __syncthreads();
    for (int o = 64; o > 0; o >>= 1) {
        if (t < o) { s1[t] += s1[t + o]; s2[t] += s2[t + o]; }
        __syncthreads();
    }
    float m   = s1[0] * (1.f / 128.f);
    float var = fmaxf(s2[0] * (1.f / 128.f) - m * m, 0.f);
    h0[(size_t)t * M3 + col] = (v - m) * rsqrtf(var + EPSV) * g[col] + b[col];
}

// ---------------- tiny MLP layers (128 graphs) ------------------------------
__global__ void mlp_layer(const float* __restrict__ X, int ldx,
                          const float* __restrict__ W, int ldw,
                          const float* __restrict__ bias,
                          float* __restrict__ Y, int ldy, int K, int doRelu) {
    int o = blockIdx.x;       // output channel
    int gI = threadIdx.x;     // graph (128)
    const float* w  = W + (size_t)o * ldw;
    const float* xr = X + (size_t)gI * ldx;
    float acc = 0.f;
    for (int k = 0; k < K; k++) acc = fmaf(xr[k], __ldg(&w[k]), acc);
    acc += bias[o];
    if (doRelu) acc = fmaxf(acc, 0.f);
    Y[(size_t)gI * ldy + o] = acc;
}

__global__ void head_kernel(const float* __restrict__ h2,
                            const float* __restrict__ w3,
                            const float* __restrict__ b3,
                            float* __restrict__ out) {
    int gI = threadIdx.x;     // 128 graphs
    float l0 = b3[0], l1 = b3[1];
    const float* xr = h2 + (size_t)gI * MM;
    for (int k = 0; k < MM; k++) {
        float x = xr[k];
        l0 = fmaf(x, __ldg(&w3[k]), l0);
        l1 = fmaf(x, __ldg(&w3[MM + k]), l1);
    }
    float mx  = fmaxf(l0, l1);
    float lse = mx + logf(expf(l0 - mx) + expf(l1 - mx));
    out[gI * 2 + 0] = l0 - lse;
    out[gI * 2 + 1] = l1 - lse;
}

// ---------------- launcher ---------------------------------------------------
extern "C" void kernel_launch(void* const* d_in, const int* in_sizes, int n_in,
                              void* d_out, int out_size) {
    const float* x       = (const float*)d_in[0];
    const int*   eidx    = (const int*)d_in[1];
    const int*   batch   = (const int*)d_in[2];
    // d_in[3] = n_graphs (constant 128)
    const float* w_rel   = (const float*)d_in[4];
    const float* b_rel   = (const float*)d_in[5];
    const float* w_root  = (const float*)d_in[6];
    const float* norm0_g = (const float*)d_in[7];
    const float* norm0_b = (const float*)d_in[8];
    const float* lin_w   = (const float*)d_in[9];
    const float* lin_b   = (const float*)d_in[10];
    const float* bnh_g   = (const float*)d_in[11];
    const float* bnh_b   = (const float*)d_in[12];
    const float* bno_g   = (const float*)d_in[13];
    const float* bno_b   = (const float*)d_in[14];
    const float* w1      = (const float*)d_in[15];
    const float* b1      = (const float*)d_in[16];
    const float* w2      = (const float*)d_in[17];
    const float* b2      = (const float*)d_in[18];
    const float* w3      = (const float*)d_in[19];
    const float* b3      = (const float*)d_in[20];
    float* out = (float*)d_out;

    const int* row = eidx;        // edge_index[0]
    const int* col = eidx + NE;   // edge_index[1]

    float *neigh, *Hc, *Hm, *Hadd, *Hmax, *cnt;
    float *sum0, *ssq0, *scale0, *shift0, *sumH, *ssqH, *scaleH, *shiftH;
    float *h0, *h1, *h2;
    cudaGetSymbolAddress((void**)&neigh,  g_neigh);
    cudaGetSymbolAddress((void**)&Hc,     g_Hc);
    cudaGetSymbolAddress((void**)&Hm,     g_Hm);
    cudaGetSymbolAddress((void**)&Hadd,   g_Hadd);
    cudaGetSymbolAddress((void**)&Hmax,   g_Hmax);
    cudaGetSymbolAddress((void**)&cnt,    g_cnt);
    cudaGetSymbolAddress((void**)&sum0,   g_sum0);
    cudaGetSymbolAddress((void**)&ssq0,   g_ssq0);
    cudaGetSymbolAddress((void**)&scale0, g_scale0);
    cudaGetSymbolAddress((void**)&shift0, g_shift0);
    cudaGetSymbolAddress((void**)&sumH,   g_sumH);
    cudaGetSymbolAddress((void**)&ssqH,   g_ssqH);
    cudaGetSymbolAddress((void**)&scaleH, g_scaleH);
    cudaGetSymbolAddress((void**)&shiftH, g_shiftH);
    cudaGetSymbolAddress((void**)&h0,     g_h0);
    cudaGetSymbolAddress((void**)&h1,     g_h1);
    cudaGetSymbolAddress((void**)&h2,     g_h2);

    // ---- init scratch (graph-replay safe) ----
    fill_f<<<2048, 256>>>(neigh, (size_t)NN * CIN, 0.f);
    fill_f<<<4096, 256>>>(Hc, (size_t)NN * MM, 0.f);
    fill_f<<<64, 256>>>(Hadd, (size_t)NG * MM, 0.f);
    fill_f<<<64, 256>>>(Hmax, (size_t)NG * MM, -INFINITY);
    fill_f<<<1, 128>>>(cnt, (size_t)NG, 0.f);
    fill_f<<<1, 256>>>(sum0, (size_t)PROJ, 0.f);
    fill_f<<<1, 256>>>(ssq0, (size_t)PROJ, 0.f);
    fill_f<<<2, 256>>>(sumH, (size_t)MM, 0.f);
    fill_f<<<2, 256>>>(ssqH, (size_t)MM, 0.f);

    dim3 sblk(32, 8);
    int sgrid = (NE + 7) / 8;
    int ggrid = (NN + 127) / 128;

    // ---- GraphConv: neigh = segment_sum(x[row], col) ----
    scatter_add<<<sgrid, sblk>>>(x, CIN, neigh, CIN, row, col, NE);

    // X_pre (Hc cols 0:128) = x @ w_root^T + b_rel ; += neigh @ w_rel^T
    sgemm_tn<<<ggrid, 256>>>(x, CIN, w_root, CIN, b_rel, Hc, MM, NN, CIN, 0);
    sgemm_tn<<<ggrid, 256>>>(neigh, CIN, w_rel, CIN, nullptr, Hc, MM, NN, CIN, 1);

    // BN0 stats + apply in place
    colstats<<<512, PROJ>>>(Hc, MM, NN, sum0, ssq0);
    mkaffine<<<1, PROJ>>>(sum0, ssq0, norm0_g, norm0_b, scale0, shift0, PROJ, 1.f / NN);
    applybn<<<2048, 256>>>(Hc, MM, PROJ, NN, scale0, shift0);

    // ---- k-hop diffusion: H1 = A X ; H2 = A H1 (cols 128:256, 256:384) ----
    scatter_add<<<sgrid, sblk>>>(Hc, MM, Hc + PROJ, MM, col, row, NE);
    scatter_add<<<sgrid, sblk>>>(Hc + PROJ, MM, Hc + 2 * PROJ, MM, col, row, NE);

    // ---- masked lin: 3 slices with K = 128 / 256 / 384 (mask structure) ----
    sgemm_tn<<<ggrid, 256>>>(Hc, MM, lin_w,                MM, lin_b,       Hm,       MM, NN, 128, 0);
    sgemm_tn<<<ggrid, 256>>>(Hc, MM, lin_w + 128 * MM,     MM, lin_b + 128, Hm + 128, MM, NN, 256, 0);
    sgemm_tn<<<ggrid, 256>>>(Hc, MM, lin_w + 256 * MM,     MM, lin_b + 256, Hm + 256, MM, NN, 384, 0);

    // BN over nodes (stats only; affine fused into pooling)
    colstats<<<512, MM>>>(Hm, MM, NN, sumH, ssqH);
    mkaffine<<<2, 256>>>(sumH, ssqH, bnh_g, bnh_b, scaleH, shiftH, MM, 1.f / NN);

    // ---- pooling (add / max / count), batch sorted ----
    pool_kernel<<<(NN + POOL_NPB - 1) / POOL_NPB, 384>>>(
        Hm, scaleH, shiftH, batch, NN, Hadd, Hmax, cnt);

    // ---- graph BN over [avg|add|max] concat ----
    bn_graphs<<<M3, 128>>>(Hadd, Hmax, cnt, bno_g, bno_b, h0);

    // ---- funnel MLP + log_softmax ----
    mlp_layer<<<768, 128>>>(h0, M3, w1, M3, b1, h1, 768, M3, 1);
    mlp_layer<<<MM, 128>>>(h1, 768, w2, 768, b2, h2, MM, 768, 1);
    head_kernel<<<1, 128>>>(h2, w3, b3, out);
}

// round 4
// speedup vs baseline: 1.1719x; 1.1719x over previous
#include <cuda_runtime.h>
#include <math.h>
#include <stdint.h>

// Problem constants (fixed by the dataset)
#define NN   50000
#define NE   600000
#define NG   128
#define CIN  128
#define PROJ 128
#define MM   384          // OUT_CH * K
#define M3   1152         // 3 * MM
#define EPSV 1e-5f

// ---------------- scratch (static device globals; no allocation allowed) ---
__device__ float g_neigh[(size_t)NN * CIN];     // 25.6 MB
__device__ float g_Hc[(size_t)NN * MM];         // 76.8 MB  [X | H1 | H2]
__device__ float g_Hm[(size_t)NN * MM];         // 76.8 MB  pre-BN hidden
__device__ float g_Hadd[NG * MM];
__device__ float g_Hmax[NG * MM];
__device__ float g_cnt[NG];
__device__ float g_sum0[PROJ], g_ssq0[PROJ], g_scale0[PROJ], g_shift0[PROJ];
__device__ float g_sumH[MM],  g_ssqH[MM],  g_scaleH[MM],  g_shiftH[MM];
__device__ float g_h0[NG * M3];
__device__ float g_h1[NG * 768];
__device__ float g_h2[NG * MM];

// CSR scratch
__device__ int g_deg[2 * NN];            // [deg_in | deg_out]
__device__ int g_off_in[NN + 1];
__device__ int g_off_out[NN + 1];
__device__ int g_cur[2 * NN];            // cursors [in | out]
__device__ int g_adj_in[NE];             // src rows grouped by dst=col
__device__ int g_adj_out[NE];            // src cols grouped by dst=row

// ---------------- helpers ---------------------------------------------------
__device__ __forceinline__ void atomicMaxF(float* addr, float v) {
    if (v >= 0.f) atomicMax((int*)addr, __float_as_int(v));
    else          atomicMin((unsigned int*)addr, (unsigned int)__float_as_int(v));
}

__global__ void fill_f(float* p, size_t n, float v) {
    size_t i  = (size_t)blockIdx.x * blockDim.x + threadIdx.x;
    size_t st = (size_t)gridDim.x * blockDim.x;
    for (; i < n; i += st) p[i] = v;
}

__global__ void fill_i(int* p, size_t n, int v) {
    size_t i  = (size_t)blockIdx.x * blockDim.x + threadIdx.x;
    size_t st = (size_t)gridDim.x * blockDim.x;
    for (; i < n; i += st) p[i] = v;
}

// ---------------- CSR build --------------------------------------------------
__global__ void count_deg(const int* __restrict__ row, const int* __restrict__ col,
                          int E, int* deg_in, int* deg_out) {
    int e = blockIdx.x * blockDim.x + threadIdx.x;
    if (e >= E) return;
    atomicAdd(&deg_in[col[e]], 1);
    atomicAdd(&deg_out[row[e]], 1);
}

// single-block exclusive scan over both degree arrays (n = NN each)
__global__ void __launch_bounds__(1024)
exscan2(const int* deg_in, int* off_in, const int* deg_out, int* off_out, int n) {
    __shared__ int sh[1024];
    __shared__ int carry;
    const int tid = threadIdx.x;
    for (int pass = 0; pass < 2; pass++) {
        const int* deg = pass ? deg_out : deg_in;
        int*       off = pass ? off_out : off_in;
        if (tid == 0) carry = 0;
        __syncthreads();
        for (int base = 0; base < n; base += 1024) {
            int i = base + tid;
            int v = (i < n) ? deg[i] : 0;
            sh[tid] = v;
            __syncthreads();
#pragma unroll
            for (int o = 1; o < 1024; o <<= 1) {
                int t = (tid >= o) ? sh[tid - o] : 0;
                __syncthreads();
                sh[tid] += t;
                __syncthreads();
            }
            if (i < n) off[i] = carry + sh[tid] - v;   // exclusive
            __syncthreads();
            if (tid == 1023) carry += sh[1023];
            __syncthreads();
        }
        if (tid == 0) off[n] = carry;
        __syncthreads();
    }
}

__global__ void copy_cursor(const int* off_in, const int* off_out, int* cur, int n) {
    int i = blockIdx.x * blockDim.x + threadIdx.x;
    if (i >= n) return;
    cur[i]     = off_in[i];
    cur[n + i] = off_out[i];
}

__global__ void build_lists(const int* __restrict__ row, const int* __restrict__ col,
                            int E, int* cur, int* adj_in, int* adj_out, int n) {
    int e = blockIdx.x * blockDim.x + threadIdx.x;
    if (e >= E) return;
    int r = row[e], c = col[e];
    int p1 = atomicAdd(&cur[c], 1);        // in-list for dst=c
    adj_in[p1] = r;
    int p2 = atomicAdd(&cur[n + r], 1);    // out-list for dst=r
    adj_out[p2] = c;
}

// ---------------- gather SpMM: dst[d] = sum over adj list of src rows -------
// one warp per destination node; 32 lanes x float4 = 128 channels.
// 2-way unrolled neighbor loop for memory-level parallelism.
__global__ void __launch_bounds__(256)
gather_spmm(const float* __restrict__ src, int lds,
            float* __restrict__ dst, int ldd,
            const int* __restrict__ off, const int* __restrict__ adj, int N) {
    int node = blockIdx.x * blockDim.y + threadIdx.y;
    if (node >= N) return;
    int s = off[node], e = off[node + 1];
    int lane = threadIdx.x;
    float4 acc0 = make_float4(0.f, 0.f, 0.f, 0.f);
    float4 acc1 = make_float4(0.f, 0.f, 0.f, 0.f);
    int i = s;
    for (; i + 1 < e; i += 2) {
        int sr0 = __ldg(&adj[i]);
        int sr1 = __ldg(&adj[i + 1]);
        float4 v0 = *(const float4*)(src + (size_t)sr0 * lds + lane * 4);
        float4 v1 = *(const float4*)(src + (size_t)sr1 * lds + lane * 4);
        acc0.x += v0.x; acc0.y += v0.y; acc0.z += v0.z; acc0.w += v0.w;
        acc1.x += v1.x; acc1.y += v1.y; acc1.z += v1.z; acc1.w += v1.w;
    }
    if (i < e) {
        int sr = __ldg(&adj[i]);
        float4 v = *(const float4*)(src + (size_t)sr * lds + lane * 4);
        acc0.x += v.x; acc0.y += v.y; acc0.z += v.z; acc0.w += v.w;
    }
    acc0.x += acc1.x; acc0.y += acc1.y; acc0.z += acc1.z; acc0.w += acc1.w;
    *(float4*)(dst + (size_t)node * ldd + lane * 4) = acc0;
}

// ---------------- SIMT sgemm: C[N,128] = A[N,K] @ W[128,K]^T (+bias / +=) ---
__global__ void __launch_bounds__(256)
sgemm_tn(const float* __restrict__ A, int lda,
         const float* __restrict__ W, int ldw,
         const float* __restrict__ bias,
         float* __restrict__ C, int ldc,
         int N, int K, int accumulate) {
    __shared__ float As[8][128];
    __shared__ float Bs[8][128];
    const int tid  = threadIdx.x;
    const int row0 = blockIdx.x * 128;
    const int lr   = tid >> 1;        // 0..127
    const int lk   = (tid & 1) * 4;   // 0 or 4
    const int tx   = tid & 15;        // 0..15
    const int ty   = tid >> 4;        // 0..15

    float acc[8][8];
#pragma unroll
    for (int i = 0; i < 8; i++)
#pragma unroll
        for (int j = 0; j < 8; j++) acc[i][j] = 0.f;

    for (int k0 = 0; k0 < K; k0 += 8) {
        float4 av = make_float4(0.f, 0.f, 0.f, 0.f);
        int ar = row0 + lr;
        if (ar < N) av = *(const float4*)(A + (size_t)ar * lda + k0 + lk);
        As[lk + 0][lr] = av.x; As[lk + 1][lr] = av.y;
        As[lk + 2][lr] = av.z; As[lk + 3][lr] = av.w;

        float4 wv = *(const float4*)(W + (size_t)lr * ldw + k0 + lk);
        Bs[lk + 0][lr] = wv.x; Bs[lk + 1][lr] = wv.y;
        Bs[lk + 2][lr] = wv.z; Bs[lk + 3][lr] = wv.w;
        __syncthreads();

#pragma unroll
        for (int k = 0; k < 8; k++) {
            float ra[8], rb[8];
#pragma unroll
            for (int i = 0; i < 8; i++) ra[i] = As[k][ty * 8 + i];
#pragma unroll
            for (int j = 0; j < 8; j++) rb[j] = Bs[k][tx * 8 + j];
#pragma unroll
            for (int i = 0; i < 8; i++)
#pragma unroll
                for (int j = 0; j < 8; j++) acc[i][j] = fmaf(ra[i], rb[j], acc[i][j]);
        }
        __syncthreads();
    }

#pragma unroll
    for (int i = 0; i < 8; i++) {
        int r = row0 + ty * 8 + i;
        if (r >= N) continue;
        float* crow = C + (size_t)r * ldc + tx * 8;
        if (accumulate) {
#pragma unroll
            for (int j = 0; j < 8; j++) crow[j] += acc[i][j];
        } else {
#pragma unroll
            for (int j = 0; j < 8; j++) {
                float b = bias ? bias[tx * 8 + j] : 0.f;
                crow[j] = acc[i][j] + b;
            }
        }
    }
}

// ---------------- column-wise sum / sumsq (BN stats over nodes) -------------
__global__ void colstats(const float* __restrict__ A, int lda, int N,
                         float* sum, float* ssq) {
    int c = threadIdx.x;
    float s = 0.f, q = 0.f;
    for (int r = blockIdx.x; r < N; r += gridDim.x) {
        float v = A[(size_t)r * lda + c];
        s += v;
        q += v * v;
    }
    atomicAdd(&sum[c], s);
    atomicAdd(&ssq[c], q);
}

__global__ void mkaffine(const float* sum, const float* ssq,
                         const float* g, const float* b,
                         float* scale, float* shift, int C, float invN) {
    int c = blockIdx.x * blockDim.x + threadIdx.x;
    if (c >= C) return;
    float m  = sum[c] * invN;
    float v  = fmaxf(ssq[c] * invN - m * m, 0.f);
    float sc = g[c] * rsqrtf(v + EPSV);
    scale[c] = sc;
    shift[c] = b[c] - m * sc;
}

__global__ void applybn(float* A, int lda, int C, int N,
                        const float* __restrict__ scale,
                        const float* __restrict__ shift) {
    size_t total = (size_t)N * C;
    size_t i  = (size_t)blockIdx.x * blockDim.x + threadIdx.x;
    size_t st = (size_t)gridDim.x * blockDim.x;
    for (; i < total; i += st) {
        int r = (int)(i / C), c = (int)(i % C);
        float* p = A + (size_t)r * lda + c;
        *p = fmaf(*p, scale[c], shift[c]);
    }
}

// ---------------- fused BN-apply + segment add/max pooling ------------------
#define POOL_NPB 64
__global__ void __launch_bounds__(384)
pool_kernel(const float* __restrict__ Hm,
            const float* __restrict__ scale, const float* __restrict__ shift,
            const int* __restrict__ batch, int N,
            float* Hadd, float* Hmax, float* cnt) {
    __shared__ int sb[POOL_NPB];
    int c  = threadIdx.x;
    int n0 = blockIdx.x * POOL_NPB;
    int nEnd = min(n0 + POOL_NPB, N);
    if (c < POOL_NPB && n0 + c < N) sb[c] = batch[n0 + c];
    __syncthreads();

    float sc = scale[c], sh = shift[c];
    float accA = 0.f, accM = -INFINITY, accC = 0.f;
    int curg = -1;
    for (int n = n0; n < nEnd; n++) {
        int g = sb[n - n0];
        if (g != curg) {
            if (curg >= 0) {
                atomicAdd(&Hadd[(size_t)curg * MM + c], accA);
                atomicMaxF(&Hmax[(size_t)curg * MM + c], accM);
                if (c == 0) atomicAdd(&cnt[curg], accC);
            }
            accA = 0.f; accM = -INFINITY; accC = 0.f; curg = g;
        }
        float v = fmaf(Hm[(size_t)n * MM + c], sc, sh);
        accA += v;
        accM = fmaxf(accM, v);
        accC += 1.f;
    }
    if (curg >= 0) {
        atomicAdd(&Hadd[(size_t)curg * MM + c], accA);
        atomicMaxF(&Hmax[(size_t)curg * MM + c], accM);
        if (c == 0) atomicAdd(&cnt[curg], accC);
    }
}

// ---------------- BN over graphs (128 rows) for the 1152-col concat ---------
__global__ void bn_graphs(const float* __restrict__ Hadd,
                          const float* __restrict__ Hmax,
                          const float* __restrict__ cnt,
                          const float* __restrict__ g,
                          const float* __restrict__ b,
                          float* __restrict__ h0) {
    int col = blockIdx.x;
    int t   = threadIdx.x;
    float v;
    if (col < MM) {
        v = Hadd[(size_t)t * MM + col] / fmaxf(cnt[t], 1.f);
    } else if (col < 2 * MM) {
        v = Hadd[(size_t)t * MM + (col - MM)];
    } else {
        v = Hmax[(size_t)t * MM + (col - 2 * MM)];
        if (!isfinite(v)) v = 0.f;
    }
    __shared__ float s1[128], s2[128];
    s1[t] = v; s2[t] = v * v;
    __syncthreads();
    for (int o = 64; o > 0; o >>= 1) {
        if (t < o) { s1[t] += s1[t + o]; s2[t] += s2[t + o]; }
        __syncthreads();
    }
    float m   = s1[0] * (1.f / 128.f);
    float var = fmaxf(s2[0] * (1.f / 128.f) - m * m, 0.f);
    h0[(size_t)t * M3 + col] = (v - m) * rsqrtf(var + EPSV) * g[col] + b[col];
}

// ---------------- tiny MLP layers (128 graphs) ------------------------------
__global__ void mlp_layer(const float* __restrict__ X, int ldx,
                          const float* __restrict__ W, int ldw,
                          const float* __restrict__ bias,
                          float* __restrict__ Y, int ldy, int K, int doRelu) {
    int o = blockIdx.x;
    int gI = threadIdx.x;
    const float* w  = W + (size_t)o * ldw;
    const float* xr = X + (size_t)gI * ldx;
    float acc = 0.f;
    for (int k = 0; k < K; k++) acc = fmaf(xr[k], __ldg(&w[k]), acc);
    acc += bias[o];
    if (doRelu) acc = fmaxf(acc, 0.f);
    Y[(size_t)gI * ldy + o] = acc;
}

__global__ void head_kernel(const float* __restrict__ h2,
                            const float* __restrict__ w3,
                            const float* __restrict__ b3,
                            float* __restrict__ out) {
    int gI = threadIdx.x;
    float l0 = b3[0], l1 = b3[1];
    const float* xr = h2 + (size_t)gI * MM;
    for (int k = 0; k < MM; k++) {
        float x = xr[k];
        l0 = fmaf(x, __ldg(&w3[k]), l0);
        l1 = fmaf(x, __ldg(&w3[MM + k]), l1);
    }
    float mx  = fmaxf(l0, l1);
    float lse = mx + logf(expf(l0 - mx) + expf(l1 - mx));
    out[gI * 2 + 0] = l0 - lse;
    out[gI * 2 + 1] = l1 - lse;
}

// ---------------- launcher ---------------------------------------------------
extern "C" void kernel_launch(void* const* d_in, const int* in_sizes, int n_in,
                              void* d_out, int out_size) {
    const float* x       = (const float*)d_in[0];
    const int*   eidx    = (const int*)d_in[1];
    const int*   batch   = (const int*)d_in[2];
    const float* w_rel   = (const float*)d_in[4];
    const float* b_rel   = (const float*)d_in[5];
    const float* w_root  = (const float*)d_in[6];
    const float* norm0_g = (const float*)d_in[7];
    const float* norm0_b = (const float*)d_in[8];
    const float* lin_w   = (const float*)d_in[9];
    const float* lin_b   = (const float*)d_in[10];
    const float* bnh_g   = (const float*)d_in[11];
    const float* bnh_b   = (const float*)d_in[12];
    const float* bno_g   = (const float*)d_in[13];
    const float* bno_b   = (const float*)d_in[14];
    const float* w1      = (const float*)d_in[15];
    const float* b1      = (const float*)d_in[16];
    const float* w2      = (const float*)d_in[17];
    const float* b2      = (const float*)d_in[18];
    const float* w3      = (const float*)d_in[19];
    const float* b3      = (const float*)d_in[20];
    float* out = (float*)d_out;

    const int* row = eidx;        // edge_index[0]
    const int* col = eidx + NE;   // edge_index[1]

    float *neigh, *Hc, *Hm, *Hadd, *Hmax, *cnt;
    float *sum0, *ssq0, *scale0, *shift0, *sumH, *ssqH, *scaleH, *shiftH;
    float *h0, *h1, *h2;
    int *deg, *off_in, *off_out, *cur, *adj_in, *adj_out;
    cudaGetSymbolAddress((void**)&neigh,  g_neigh);
    cudaGetSymbolAddress((void**)&Hc,     g_Hc);
    cudaGetSymbolAddress((void**)&Hm,     g_Hm);
    cudaGetSymbolAddress((void**)&Hadd,   g_Hadd);
    cudaGetSymbolAddress((void**)&Hmax,   g_Hmax);
    cudaGetSymbolAddress((void**)&cnt,    g_cnt);
    cudaGetSymbolAddress((void**)&sum0,   g_sum0);
    cudaGetSymbolAddress((void**)&ssq0,   g_ssq0);
    cudaGetSymbolAddress((void**)&scale0, g_scale0);
    cudaGetSymbolAddress((void**)&shift0, g_shift0);
    cudaGetSymbolAddress((void**)&sumH,   g_sumH);
    cudaGetSymbolAddress((void**)&ssqH,   g_ssqH);
    cudaGetSymbolAddress((void**)&scaleH, g_scaleH);
    cudaGetSymbolAddress((void**)&shiftH, g_shiftH);
    cudaGetSymbolAddress((void**)&h0,     g_h0);
    cudaGetSymbolAddress((void**)&h1,     g_h1);
    cudaGetSymbolAddress((void**)&h2,     g_h2);
    cudaGetSymbolAddress((void**)&deg,     g_deg);
    cudaGetSymbolAddress((void**)&off_in,  g_off_in);
    cudaGetSymbolAddress((void**)&off_out, g_off_out);
    cudaGetSymbolAddress((void**)&cur,     g_cur);
    cudaGetSymbolAddress((void**)&adj_in,  g_adj_in);
    cudaGetSymbolAddress((void**)&adj_out, g_adj_out);

    // ===== CSR build (launches #1-#5; #6 = first gather, ncu-profiled) =====
    fill_i<<<256, 256>>>(deg, (size_t)2 * NN, 0);                          // 1
    count_deg<<<(NE + 255) / 256, 256>>>(row, col, NE, deg, deg + NN);     // 2
    exscan2<<<1, 1024>>>(deg, off_in, deg + NN, off_out, NN);              // 3
    copy_cursor<<<(NN + 255) / 256, 256>>>(off_in, off_out, cur, NN);      // 4
    build_lists<<<(NE + 255) / 256, 256>>>(row, col, NE, cur, adj_in, adj_out, NN); // 5

    dim3 gblk(32, 8);
    int ggrid_n = (NN + 7) / 8;
    int ggrid = (NN + 127) / 128;

    // ---- GraphConv neighbor sum via gather (launch #6, profiled) ----
    gather_spmm<<<ggrid_n, gblk>>>(x, CIN, neigh, CIN, off_in, adj_in, NN); // 6

    // ---- small inits ----
    fill_f<<<64, 256>>>(Hadd, (size_t)NG * MM, 0.f);
    fill_f<<<64, 256>>>(Hmax, (size_t)NG * MM, -INFINITY);
    fill_f<<<1, 128>>>(cnt, (size_t)NG, 0.f);
    fill_f<<<1, 256>>>(sum0, (size_t)PROJ, 0.f);
    fill_f<<<1, 256>>>(ssq0, (size_t)PROJ, 0.f);
    fill_f<<<2, 256>>>(sumH, (size_t)MM, 0.f);
    fill_f<<<2, 256>>>(ssqH, (size_t)MM, 0.f);

    // X_pre (Hc cols 0:128) = x @ w_root^T + b_rel ; += neigh @ w_rel^T
    sgemm_tn<<<ggrid, 256>>>(x, CIN, w_root, CIN, b_rel, Hc, MM, NN, CIN, 0);
    sgemm_tn<<<ggrid, 256>>>(neigh, CIN, w_rel, CIN, nullptr, Hc, MM, NN, CIN, 1);

    // BN0 stats + apply in place
    colstats<<<512, PROJ>>>(Hc, MM, NN, sum0, ssq0);
    mkaffine<<<1, PROJ>>>(sum0, ssq0, norm0_g, norm0_b, scale0, shift0, PROJ, 1.f / NN);
    applybn<<<2048, 256>>>(Hc, MM, PROJ, NN, scale0, shift0);

    // ---- k-hop diffusion via gather: H1 = A X ; H2 = A H1 ----
    gather_spmm<<<ggrid_n, gblk>>>(Hc, MM, Hc + PROJ, MM, off_out, adj_out, NN);
    gather_spmm<<<ggrid_n, gblk>>>(Hc + PROJ, MM, Hc + 2 * PROJ, MM, off_out, adj_out, NN);

    // ---- masked lin: 3 slices with K = 128 / 256 / 384 (mask structure) ----
    sgemm_tn<<<ggrid, 256>>>(Hc, MM, lin_w,            MM, lin_b,       Hm,       MM, NN, 128, 0);
    sgemm_tn<<<ggrid, 256>>>(Hc, MM, lin_w + 128 * MM, MM, lin_b + 128, Hm + 128, MM, NN, 256, 0);
    sgemm_tn<<<ggrid, 256>>>(Hc, MM, lin_w + 256 * MM, MM, lin_b + 256, Hm + 256, MM, NN, 384, 0);

    // BN over nodes (stats only; affine fused into pooling)
    colstats<<<512, MM>>>(Hm, MM, NN, sumH, ssqH);
    mkaffine<<<2, 256>>>(sumH, ssqH, bnh_g, bnh_b, scaleH, shiftH, MM, 1.f / NN);

    // ---- pooling (add / max / count), batch sorted ----
    pool_kernel<<<(NN + POOL_NPB - 1) / POOL_NPB, 384>>>(
        Hm, scaleH, shiftH, batch, NN, Hadd, Hmax, cnt);

    // ---- graph BN over [avg|add|max] concat ----
    bn_graphs<<<M3, 128>>>(Hadd, Hmax, cnt, bno_g, bno_b, h0);

    // ---- funnel MLP + log_softmax ----
    mlp_layer<<<768, 128>>>(h0, M3, w1, M3, b1, h1, 768, M3, 1);
    mlp_layer<<<MM, 128>>>(h1, 768, w2, 768, b2, h2, MM, 768, 1);
    head_kernel<<<1, 128>>>(h2, w3, b3, out);
}

// round 6
// speedup vs baseline: 1.2930x; 1.1033x over previous
#include <cuda_runtime.h>
#include <cuda_bf16.h>
#include <math.h>
#include <stdint.h>

// Problem constants (fixed by the dataset)
#define NN   50000
#define NE   600000
#define NG   128
#define CIN  128
#define PROJ 128
#define MM   384          // OUT_CH * K
#define M3   1152         // 3 * MM
#define EPSV 1e-5f

// ---------------- scratch (static device globals; no allocation allowed) ---
__device__ float g_neigh[(size_t)NN * CIN];
__device__ float g_Hc[(size_t)NN * MM];
__device__ float g_Hm[(size_t)NN * MM];
__device__ float g_Hadd[NG * MM];
__device__ float g_Hmax[NG * MM];
__device__ float g_cnt[NG];
__device__ float g_sum0[PROJ], g_ssq0[PROJ], g_scale0[PROJ], g_shift0[PROJ];
__device__ float g_sumH[MM],  g_ssqH[MM],  g_scaleH[MM],  g_shiftH[MM];
__device__ float g_h0[NG * M3];
__device__ float g_h1[NG * 768];
__device__ float g_h2[NG * MM];

// CSR scratch
__device__ int g_deg[2 * NN];
__device__ int g_off_in[NN + 1];
__device__ int g_off_out[NN + 1];
__device__ int g_cur[2 * NN];
__device__ int g_adj_in[NE];
__device__ int g_adj_out[NE];

// bf16 hi/lo weight scratch
__device__ __nv_bfloat16 g_wrt_hi[128 * 128], g_wrt_lo[128 * 128];   // w_root
__device__ __nv_bfloat16 g_wrl_hi[128 * 128], g_wrl_lo[128 * 128];   // w_rel
__device__ __nv_bfloat16 g_wl_hi[384 * 384],  g_wl_lo[384 * 384];    // lin_w

// ---------------- small helpers ---------------------------------------------
__device__ __forceinline__ uint32_t smem_u32(const void* p) {
    uint32_t a;
    asm("{ .reg .u64 t; cvta.to.shared.u64 t, %1; cvt.u32.u64 %0, t; }"
        : "=r"(a) : "l"(p));
    return a;
}
__device__ __forceinline__ void split_bf16(float v, __nv_bfloat16* hi, __nv_bfloat16* lo) {
    __nv_bfloat16 h = __float2bfloat16(v);
    *hi = h;
    *lo = __float2bfloat16(v - __bfloat162float(h));
}

__global__ void prep_w(const float* __restrict__ w_root, const float* __restrict__ w_rel,
                       const float* __restrict__ lin_w) {
    int i = blockIdx.x * blockDim.x + threadIdx.x;
    if (i < 128 * 128) {
        split_bf16(w_root[i], &g_wrt_hi[i], &g_wrt_lo[i]);
        split_bf16(w_rel[i],  &g_wrl_hi[i], &g_wrl_lo[i]);
    }
    if (i < 384 * 384) {
        split_bf16(lin_w[i], &g_wl_hi[i], &g_wl_lo[i]);
    }
}

// ================= HMMA GEMM (mma.sync bf16, hi/lo split, fp32 accum) =======
// C[row0:row0+128, col0:col0+128] = sum_c A_c[128,128] @ W[col0+.., c*128+..]^T
// A fp32 (split on the fly), W pre-split bf16 hi/lo, [out, k] row-major.
#define SA 136                         // SMEM row stride in bf16 (128 + 8 pad)
#define HM_SMEM (4 * 128 * SA * 2)     // 4 buffers (Ahi, Alo, Whi, Wlo)

#define LDM_X4(r, a) \
    asm volatile("ldmatrix.sync.aligned.m8n8.x4.shared.b16 {%0,%1,%2,%3}, [%4];" \
                 : "=r"((r)[0]), "=r"((r)[1]), "=r"((r)[2]), "=r"((r)[3]) : "r"(a))
#define LDM_X2(r, a) \
    asm volatile("ldmatrix.sync.aligned.m8n8.x2.shared.b16 {%0,%1}, [%2];" \
                 : "=r"((r)[0]), "=r"((r)[1]) : "r"(a))
#define MMA16816(c, a, b) \
    asm volatile("mma.sync.aligned.m16n8k16.row.col.f32.bf16.bf16.f32 " \
                 "{%0,%1,%2,%3}, {%4,%5,%6,%7}, {%8,%9}, {%0,%1,%2,%3};" \
                 : "+f"((c)[0]), "+f"((c)[1]), "+f"((c)[2]), "+f"((c)[3]) \
                 : "r"((a)[0]), "r"((a)[1]), "r"((a)[2]), "r"((a)[3]), \
                   "r"((b)[0]), "r"((b)[1]))

__global__ void __launch_bounds__(256, 1)
hmma_gemm(const float* A0, const float* A1, const float* A2, int lda,
          const __nv_bfloat16* __restrict__ Whi, const __nv_bfloat16* __restrict__ Wlo,
          int ktot, const float* __restrict__ bias,
          float* __restrict__ C, int ldc, int Nrows, int masked, int accumulate) {
    extern __shared__ char smem[];
    __nv_bfloat16* sAh = (__nv_bfloat16*)smem;
    __nv_bfloat16* sAl = sAh + 128 * SA;
    __nv_bfloat16* sWh = sAl + 128 * SA;
    __nv_bfloat16* sWl = sWh + 128 * SA;

    const int tid  = threadIdx.x;
    const int lane = tid & 31;
    const int warp = tid >> 5;
    const int wm   = warp >> 1;        // 0..3 (32-row strips)
    const int wn   = warp & 1;         // 0..1 (64-col strips)
    const int row0 = blockIdx.x * 128;
    const int cb   = masked ? blockIdx.y : 0;
    const int nc   = masked ? cb + 1 : 1;
    const int col0 = cb * 128;
    const float* Aps[3] = {A0, A1, A2};

    float acc[2][8][4];
#pragma unroll
    for (int mt = 0; mt < 2; mt++)
#pragma unroll
        for (int nt = 0; nt < 8; nt++)
#pragma unroll
            for (int j = 0; j < 4; j++) acc[mt][nt][j] = 0.f;

    // per-lane ldmatrix source addresses (fixed per warp)
    const int a_r  = (lane & 15);              // row within 16-row tile
    const int a_c  = (lane >> 4) * 8;          // 0 or 8 (k offset)
    const int b_r  = (lane & 7);               // row within 8-row n tile
    const int b_c  = ((lane >> 3) & 1) * 8;    // 0 or 8 (k offset)

    for (int c = 0; c < nc; c++) {
        __syncthreads();                        // SMEM free to overwrite
        const float* Ap = Aps[c];
        // ---- A chunk: 128x128 fp32 -> hi/lo bf16 SMEM ----
#pragma unroll
        for (int i = 0; i < 16; i++) {
            int idx = tid + 256 * i;            // 4096 float4s
            int r = idx >> 5, c4 = (idx & 31) * 4;
            float4 v = make_float4(0.f, 0.f, 0.f, 0.f);
            int gr = row0 + r;
            if (gr < Nrows) v = *(const float4*)(Ap + (size_t)gr * lda + c4);
            __nv_bfloat16 h, l;
            split_bf16(v.x, &h, &l); sAh[r * SA + c4 + 0] = h; sAl[r * SA + c4 + 0] = l;
            split_bf16(v.y, &h, &l); sAh[r * SA + c4 + 1] = h; sAl[r * SA + c4 + 1] = l;
            split_bf16(v.z, &h, &l); sAh[r * SA + c4 + 2] = h; sAl[r * SA + c4 + 2] = l;
            split_bf16(v.w, &h, &l); sAh[r * SA + c4 + 3] = h; sAl[r * SA + c4 + 3] = l;
        }
        // ---- W chunk: 128 (out) x 128 (k) bf16 hi/lo -> SMEM ----
#pragma unroll
        for (int i = 0; i < 32; i++) {
            int idx = tid + 256 * i;            // 8192 u32s
            int r = idx >> 6, cu = (idx & 63) * 2;
            size_t goff = (size_t)(col0 + r) * ktot + c * 128 + cu;
            *(uint32_t*)(sWh + r * SA + cu) = *(const uint32_t*)(Whi + goff);
            *(uint32_t*)(sWl + r * SA + cu) = *(const uint32_t*)(Wlo + goff);
        }
        __syncthreads();

        // ---- MMA over 8 k-steps of 16 ----
#pragma unroll
        for (int ks = 0; ks < 8; ks++) {
            int k0 = ks * 16;
            uint32_t ah[2][4], al[2][4], bh[8][2], bl[8][2];
#pragma unroll
            for (int mt = 0; mt < 2; mt++) {
                int r0 = wm * 32 + mt * 16;
                uint32_t adr_h = smem_u32(sAh + (r0 + a_r) * SA + k0 + a_c);
                uint32_t adr_l = smem_u32(sAl + (r0 + a_r) * SA + k0 + a_c);
                LDM_X4(ah[mt], adr_h);
                LDM_X4(al[mt], adr_l);
            }
#pragma unroll
            for (int nt = 0; nt < 8; nt++) {
                int n0 = wn * 64 + nt * 8;
                uint32_t adr_h = smem_u32(sWh + (n0 + b_r) * SA + k0 + b_c);
                uint32_t adr_l = smem_u32(sWl + (n0 + b_r) * SA + k0 + b_c);
                LDM_X2(bh[nt], adr_h);
                LDM_X2(bl[nt], adr_l);
            }
#pragma unroll
            for (int mt = 0; mt < 2; mt++)
#pragma unroll
                for (int nt = 0; nt < 8; nt++) {
                    MMA16816(acc[mt][nt], ah[mt], bh[nt]);
                    MMA16816(acc[mt][nt], ah[mt], bl[nt]);
                    MMA16816(acc[mt][nt], al[mt], bh[nt]);
                }
        }
    }

    // ---- epilogue ----
    const int g = lane >> 2, t = (lane & 3) * 2;
#pragma unroll
    for (int mt = 0; mt < 2; mt++) {
        int r1 = row0 + wm * 32 + mt * 16 + g;
        int r2 = r1 + 8;
#pragma unroll
        for (int nt = 0; nt < 8; nt++) {
            int cc = col0 + wn * 64 + nt * 8 + t;
            if (r1 < Nrows) {
                float* p = C + (size_t)r1 * ldc + cc;
                if (accumulate) { p[0] += acc[mt][nt][0]; p[1] += acc[mt][nt][1]; }
                else {
                    float b0 = bias ? bias[cc] : 0.f, b1 = bias ? bias[cc + 1] : 0.f;
                    p[0] = acc[mt][nt][0] + b0; p[1] = acc[mt][nt][1] + b1;
                }
            }
            if (r2 < Nrows) {
                float* p = C + (size_t)r2 * ldc + cc;
                if (accumulate) { p[0] += acc[mt][nt][2]; p[1] += acc[mt][nt][3]; }
                else {
                    float b0 = bias ? bias[cc] : 0.f, b1 = bias ? bias[cc + 1] : 0.f;
                    p[0] = acc[mt][nt][2] + b0; p[1] = acc[mt][nt][3] + b1;
                }
            }
        }
    }
}

// ---------------- misc helpers ----------------------------------------------
__device__ __forceinline__ void atomicMaxF(float* addr, float v) {
    if (v >= 0.f) atomicMax((int*)addr, __float_as_int(v));
    else          atomicMin((unsigned int*)addr, (unsigned int)__float_as_int(v));
}

__global__ void fill_f(float* p, size_t n, float v) {
    size_t i  = (size_t)blockIdx.x * blockDim.x + threadIdx.x;
    size_t st = (size_t)gridDim.x * blockDim.x;
    for (; i < n; i += st) p[i] = v;
}
__global__ void fill_i(int* p, size_t n, int v) {
    size_t i  = (size_t)blockIdx.x * blockDim.x + threadIdx.x;
    size_t st = (size_t)gridDim.x * blockDim.x;
    for (; i < n; i += st) p[i] = v;
}

// ---------------- CSR build --------------------------------------------------
__global__ void count_deg(const int* __restrict__ row, const int* __restrict__ col,
                          int E, int* deg_in, int* deg_out) {
    int e = blockIdx.x * blockDim.x + threadIdx.x;
    if (e >= E) return;
    atomicAdd(&deg_in[col[e]], 1);
    atomicAdd(&deg_out[row[e]], 1);
}

__global__ void __launch_bounds__(1024)
exscan2c(const int* deg_in, int* off_in, const int* deg_out, int* off_out,
         int* cur, int n) {
    __shared__ int sh[1024];
    __shared__ int carry;
    const int tid = threadIdx.x;
    for (int pass = 0; pass < 2; pass++) {
        const int* deg = pass ? deg_out : deg_in;
        int*       off = pass ? off_out : off_in;
        int*       cu  = pass ? cur + n : cur;
        if (tid == 0) carry = 0;
        __syncthreads();
        for (int base = 0; base < n; base += 1024) {
            int i = base + tid;
            int v = (i < n) ? deg[i] : 0;
            sh[tid] = v;
            __syncthreads();
#pragma unroll
            for (int o = 1; o < 1024; o <<= 1) {
                int tv = (tid >= o) ? sh[tid - o] : 0;
                __syncthreads();
                sh[tid] += tv;
                __syncthreads();
            }
            if (i < n) { int e = carry + sh[tid] - v; off[i] = e; cu[i] = e; }
            __syncthreads();
            if (tid == 1023) carry += sh[1023];
            __syncthreads();
        }
        if (tid == 0) off[n] = carry;
        __syncthreads();
    }
}

__global__ void build_lists(const int* __restrict__ row, const int* __restrict__ col,
                            int E, int* cur, int* adj_in, int* adj_out, int n) {
    int e = blockIdx.x * blockDim.x + threadIdx.x;
    if (e >= E) return;
    int r = row[e], c = col[e];
    int p1 = atomicAdd(&cur[c], 1);
    adj_in[p1] = r;
    int p2 = atomicAdd(&cur[n + r], 1);
    adj_out[p2] = c;
}

// ---------------- gather SpMM ------------------------------------------------
__global__ void __launch_bounds__(256)
gather_spmm(const float* __restrict__ src, int lds,
            float* __restrict__ dst, int ldd,
            const int* __restrict__ off, const int* __restrict__ adj, int N) {
    int node = blockIdx.x * blockDim.y + threadIdx.y;
    if (node >= N) return;
    int s = off[node], e = off[node + 1];
    int lane = threadIdx.x;
    float4 acc0 = make_float4(0.f, 0.f, 0.f, 0.f);
    float4 acc1 = make_float4(0.f, 0.f, 0.f, 0.f);
    int i = s;
    for (; i + 1 < e; i += 2) {
        int sr0 = __ldg(&adj[i]);
        int sr1 = __ldg(&adj[i + 1]);
        float4 v0 = *(const float4*)(src + (size_t)sr0 * lds + lane * 4);
        float4 v1 = *(const float4*)(src + (size_t)sr1 * lds + lane * 4);
        acc0.x += v0.x; acc0.y += v0.y; acc0.z += v0.z; acc0.w += v0.w;
        acc1.x += v1.x; acc1.y += v1.y; acc1.z += v1.z; acc1.w += v1.w;
    }
    if (i < e) {
        int sr = __ldg(&adj[i]);
        float4 v = *(const float4*)(src + (size_t)sr * lds + lane * 4);
        acc0.x += v.x; acc0.y += v.y; acc0.z += v.z; acc0.w += v.w;
    }
    acc0.x += acc1.x; acc0.y += acc1.y; acc0.z += acc1.z; acc0.w += acc1.w;
    *(float4*)(dst + (size_t)node * ldd + lane * 4) = acc0;
}

// ---------------- BN stats / apply ------------------------------------------
__global__ void colstats(const float* __restrict__ A, int lda, int N,
                         float* sum, float* ssq) {
    int c = threadIdx.x;
    float s = 0.f, q = 0.f;
    for (int r = blockIdx.x; r < N; r += gridDim.x) {
        float v = A[(size_t)r * lda + c];
        s += v;
        q += v * v;
    }
    atomicAdd(&sum[c], s);
    atomicAdd(&ssq[c], q);
}

__global__ void mkaffine(const float* sum, const float* ssq,
                         const float* g, const float* b,
                         float* scale, float* shift, int C, float invN) {
    int c = blockIdx.x * blockDim.x + threadIdx.x;
    if (c >= C) return;
    float m  = sum[c] * invN;
    float v  = fmaxf(ssq[c] * invN - m * m, 0.f);
    float sc = g[c] * rsqrtf(v + EPSV);
    scale[c] = sc;
    shift[c] = b[c] - m * sc;
}

__global__ void applybn(float* A, int lda, int C, int N,
                        const float* __restrict__ scale,
                        const float* __restrict__ shift) {
    size_t total = (size_t)N * C;
    size_t i  = (size_t)blockIdx.x * blockDim.x + threadIdx.x;
    size_t st = (size_t)gridDim.x * blockDim.x;
    for (; i < total; i += st) {
        int r = (int)(i / C), c = (int)(i % C);
        float* p = A + (size_t)r * lda + c;
        *p = fmaf(*p, scale[c], shift[c]);
    }
}

// ---------------- fused BN-apply + segment add/max pooling ------------------
#define POOL_NPB 64
__global__ void __launch_bounds__(384)
pool_kernel(const float* __restrict__ Hm,
            const float* __restrict__ scale, const float* __restrict__ shift,
            const int* __restrict__ batch, int N,
            float* Hadd, float* Hmax, float* cnt) {
    __shared__ int sb[POOL_NPB];
    int c  = threadIdx.x;
    int n0 = blockIdx.x * POOL_NPB;
    int nEnd = min(n0 + POOL_NPB, N);
    if (c < POOL_NPB && n0 + c < N) sb[c] = batch[n0 + c];
    __syncthreads();

    float sc = scale[c], sh = shift[c];
    float accA = 0.f, accM = -INFINITY, accC = 0.f;
    int curg = -1;
    for (int n = n0; n < nEnd; n++) {
        int g = sb[n - n0];
        if (g != curg) {
            if (curg >= 0) {
                atomicAdd(&Hadd[(size_t)curg * MM + c], accA);
                atomicMaxF(&Hmax[(size_t)curg * MM + c], accM);
                if (c == 0) atomicAdd(&cnt[curg], accC);
            }
            accA = 0.f; accM = -INFINITY; accC = 0.f; curg = g;
        }
        float v = fmaf(Hm[(size_t)n * MM + c], sc, sh);
        accA += v;
        accM = fmaxf(accM, v);
        accC += 1.f;
    }
    if (curg >= 0) {
        atomicAdd(&Hadd[(size_t)curg * MM + c], accA);
        atomicMaxF(&Hmax[(size_t)curg * MM + c], accM);
        if (c == 0) atomicAdd(&cnt[curg], accC);
    }
}

// ---------------- BN over graphs --------------------------------------------
__global__ void bn_graphs(const float* __restrict__ Hadd,
                          const float* __restrict__ Hmax,
                          const float* __restrict__ cnt,
                          const float* __restrict__ g,
                          const float* __restrict__ b,
                          float* __restrict__ h0) {
    int col = blockIdx.x;
    int t   = threadIdx.x;
    float v;
    if (col < MM) {
        v = Hadd[(size_t)t * MM + col] / fmaxf(cnt[t], 1.f);
    } else if (col < 2 * MM) {
        v = Hadd[(size_t)t * MM + (col - MM)];
    } else {
        v = Hmax[(size_t)t * MM + (col - 2 * MM)];
        if (!isfinite(v)) v = 0.f;
    }
    __shared__ float s1[128], s2[128];
    s1[t] = v; s2[t] = v * v;
    __syncthreads();
    for (int o = 64; o > 0; o >>= 1) {
        if (t < o) { s1[t] += s1[t + o]; s2[t] += s2[t + o]; }
        __syncthreads();
    }
    float m   = s1[0] * (1.f / 128.f);
    float var = fmaxf(s2[0] * (1.f / 128.f) - m * m, 0.f);
    h0[(size_t)t * M3 + col] = (v - m) * rsqrtf(var + EPSV) * g[col] + b[col];
}

// ---------------- tiny MLP layers -------------------------------------------
__global__ void mlp_layer(const float* __restrict__ X, int ldx,
                          const float* __restrict__ W, int ldw,
                          const float* __restrict__ bias,
                          float* __restrict__ Y, int ldy, int K, int doRelu) {
    int o = blockIdx.x;
    int gI = threadIdx.x;
    const float* w  = W + (size_t)o * ldw;
    const float* xr = X + (size_t)gI * ldx;
    float acc = 0.f;
    for (int k = 0; k < K; k++) acc = fmaf(xr[k], __ldg(&w[k]), acc);
    acc += bias[o];
    if (doRelu) acc = fmaxf(acc, 0.f);
    Y[(size_t)gI * ldy + o] = acc;
}

__global__ void head_kernel(const float* __restrict__ h2,
                            const float* __restrict__ w3,
                            const float* __restrict__ b3,
                            float* __restrict__ out) {
    int gI = threadIdx.x;
    float l0 = b3[0], l1 = b3[1];
    const float* xr = h2 + (size_t)gI * MM;
    for (int k = 0; k < MM; k++) {
        float x = xr[k];
        l0 = fmaf(x, __ldg(&w3[k]), l0);
        l1 = fmaf(x, __ldg(&w3[MM + k]), l1);
    }
    float mx  = fmaxf(l0, l1);
    float lse = mx + logf(expf(l0 - mx) + expf(l1 - mx));
    out[gI * 2 + 0] = l0 - lse;
    out[gI * 2 + 1] = l1 - lse;
}

// ---------------- launcher ---------------------------------------------------
extern "C" void kernel_launch(void* const* d_in, const int* in_sizes, int n_in,
                              void* d_out, int out_size) {
    const float* x       = (const float*)d_in[0];
    const int*   eidx    = (const int*)d_in[1];
    const int*   batch   = (const int*)d_in[2];
    const float* w_rel   = (const float*)d_in[4];
    const float* b_rel   = (const float*)d_in[5];
    const float* w_root  = (const float*)d_in[6];
    const float* norm0_g = (const float*)d_in[7];
    const float* norm0_b = (const float*)d_in[8];
    const float* lin_w   = (const float*)d_in[9];
    const float* lin_b   = (const float*)d_in[10];
    const float* bnh_g   = (const float*)d_in[11];
    const float* bnh_b   = (const float*)d_in[12];
    const float* bno_g   = (const float*)d_in[13];
    const float* bno_b   = (const float*)d_in[14];
    const float* w1      = (const float*)d_in[15];
    const float* b1      = (const float*)d_in[16];
    const float* w2      = (const float*)d_in[17];
    const float* b2      = (const float*)d_in[18];
    const float* w3      = (const float*)d_in[19];
    const float* b3      = (const float*)d_in[20];
    float* out = (float*)d_out;

    const int* row = eidx;
    const int* col = eidx + NE;

    float *neigh, *Hc, *Hm, *Hadd, *Hmax, *cnt;
    float *sum0, *ssq0, *scale0, *shift0, *sumH, *ssqH, *scaleH, *shiftH;
    float *h0, *h1, *h2;
    int *deg, *off_in, *off_out, *cur, *adj_in, *adj_out;
    __nv_bfloat16 *wrt_hi, *wrt_lo, *wrl_hi, *wrl_lo, *wl_hi, *wl_lo;
    cudaGetSymbolAddress((void**)&neigh,  g_neigh);
    cudaGetSymbolAddress((void**)&Hc,     g_Hc);
    cudaGetSymbolAddress((void**)&Hm,     g_Hm);
    cudaGetSymbolAddress((void**)&Hadd,   g_Hadd);
    cudaGetSymbolAddress((void**)&Hmax,   g_Hmax);
    cudaGetSymbolAddress((void**)&cnt,    g_cnt);
    cudaGetSymbolAddress((void**)&sum0,   g_sum0);
    cudaGetSymbolAddress((void**)&ssq0,   g_ssq0);
    cudaGetSymbolAddress((void**)&scale0, g_scale0);
    cudaGetSymbolAddress((void**)&shift0, g_shift0);
    cudaGetSymbolAddress((void**)&sumH,   g_sumH);
    cudaGetSymbolAddress((void**)&ssqH,   g_ssqH);
    cudaGetSymbolAddress((void**)&scaleH, g_scaleH);
    cudaGetSymbolAddress((void**)&shiftH, g_shiftH);
    cudaGetSymbolAddress((void**)&h0,     g_h0);
    cudaGetSymbolAddress((void**)&h1,     g_h1);
    cudaGetSymbolAddress((void**)&h2,     g_h2);
    cudaGetSymbolAddress((void**)&deg,     g_deg);
    cudaGetSymbolAddress((void**)&off_in,  g_off_in);
    cudaGetSymbolAddress((void**)&off_out, g_off_out);
    cudaGetSymbolAddress((void**)&cur,     g_cur);
    cudaGetSymbolAddress((void**)&adj_in,  g_adj_in);
    cudaGetSymbolAddress((void**)&adj_out, g_adj_out);
    cudaGetSymbolAddress((void**)&wrt_hi,  g_wrt_hi);
    cudaGetSymbolAddress((void**)&wrt_lo,  g_wrt_lo);
    cudaGetSymbolAddress((void**)&wrl_hi,  g_wrl_hi);
    cudaGetSymbolAddress((void**)&wrl_lo,  g_wrl_lo);
    cudaGetSymbolAddress((void**)&wl_hi,   g_wl_hi);
    cudaGetSymbolAddress((void**)&wl_lo,   g_wl_lo);

    cudaFuncSetAttribute(hmma_gemm, cudaFuncAttributeMaxDynamicSharedMemorySize, HM_SMEM);

    int ggrid = (NN + 127) / 128;        // 391 row blocks
    dim3 gblk(32, 8);
    int ggrid_n = (NN + 7) / 8;

    // #1..#3
    fill_i<<<256, 256>>>(deg, (size_t)2 * NN, 0);
    count_deg<<<(NE + 255) / 256, 256>>>(row, col, NE, deg, deg + NN);
    prep_w<<<(384 * 384 + 255) / 256, 256>>>(w_root, w_rel, lin_w);

    // #4 (ncu-profiled): Hc[:,0:128] = x @ w_root^T + b_rel
    hmma_gemm<<<dim3(ggrid, 1), 256, HM_SMEM>>>(
        x, nullptr, nullptr, CIN, wrt_hi, wrt_lo, 128, b_rel, Hc, MM, NN, 0, 0);

    // CSR scan + build + gather
    exscan2c<<<1, 1024>>>(deg, off_in, deg + NN, off_out, cur, NN);
    build_lists<<<(NE + 255) / 256, 256>>>(row, col, NE, cur, adj_in, adj_out, NN);
    gather_spmm<<<ggrid_n, gblk>>>(x, CIN, neigh, CIN, off_in, adj_in, NN);

    // Hc[:,0:128] += neigh @ w_rel^T
    hmma_gemm<<<dim3(ggrid, 1), 256, HM_SMEM>>>(
        neigh, nullptr, nullptr, CIN, wrl_hi, wrl_lo, 128, nullptr, Hc, MM, NN, 0, 1);

    // BN0 stats + apply in place
    fill_f<<<1, 256>>>(sum0, (size_t)PROJ, 0.f);
    fill_f<<<1, 256>>>(ssq0, (size_t)PROJ, 0.f);
    colstats<<<512, PROJ>>>(Hc, MM, NN, sum0, ssq0);
    mkaffine<<<1, PROJ>>>(sum0, ssq0, norm0_g, norm0_b, scale0, shift0, PROJ, 1.f / NN);
    applybn<<<2048, 256>>>(Hc, MM, PROJ, NN, scale0, shift0);

    // k-hop diffusion
    gather_spmm<<<ggrid_n, gblk>>>(Hc, MM, Hc + PROJ, MM, off_out, adj_out, NN);
    gather_spmm<<<ggrid_n, gblk>>>(Hc + PROJ, MM, Hc + 2 * PROJ, MM, off_out, adj_out, NN);

    // masked lin: 3 col-blocks, K = 128*(y+1), via HMMA
    hmma_gemm<<<dim3(ggrid, 3), 256, HM_SMEM>>>(
        Hc, Hc + 128, Hc + 256, MM, wl_hi, wl_lo, 384, lin_b, Hm, MM, NN, 1, 0);

    // BN over nodes (stats only; affine fused into pooling)
    fill_f<<<2, 256>>>(sumH, (size_t)MM, 0.f);
    fill_f<<<2, 256>>>(ssqH, (size_t)MM, 0.f);
    colstats<<<512, MM>>>(Hm, MM, NN, sumH, ssqH);
    mkaffine<<<2, 256>>>(sumH, ssqH, bnh_g, bnh_b, scaleH, shiftH, MM, 1.f / NN);

    // pooling
    fill_f<<<64, 256>>>(Hadd, (size_t)NG * MM, 0.f);
    fill_f<<<64, 256>>>(Hmax, (size_t)NG * MM, -INFINITY);
    fill_f<<<1, 128>>>(cnt, (size_t)NG, 0.f);
    pool_kernel<<<(NN + POOL_NPB - 1) / POOL_NPB, 384>>>(
        Hm, scaleH, shiftH, batch, NN, Hadd, Hmax, cnt);

    // graph BN + funnel MLP + log_softmax
    bn_graphs<<<M3, 128>>>(Hadd, Hmax, cnt, bno_g, bno_b, h0);
    mlp_layer<<<768, 128>>>(h0, M3, w1, M3, b1, h1, 768, M3, 1);
    mlp_layer<<<MM, 128>>>(h1, 768, w2, 768, b2, h2, MM, 768, 1);
    head_kernel<<<1, 128>>>(h2, w3, b3, out);
}

// round 9
// speedup vs baseline: 1.5434x; 1.1936x over previous
#include <cuda_runtime.h>
#include <cuda_bf16.h>
#include <math.h>
#include <stdint.h>

// Problem constants (fixed by the dataset)
#define NN   50000
#define NE   600000
#define NG   128
#define CIN  128
#define PROJ 128
#define MM   384          // OUT_CH * K
#define M3   1152         // 3 * MM
#define EPSV 1e-5f

// ---------------- scratch (static device globals; no allocation allowed) ---
__device__ float g_Hc[(size_t)NN * MM];         // [X | H1 | H2] fp32
__device__ float g_Hm[(size_t)NN * MM];         // pre-BN hidden
__device__ float g_Hadd[NG * MM];
__device__ float g_Hmax[NG * MM];
__device__ float g_cnt[NG];
__device__ float g_sum0[PROJ], g_ssq0[PROJ], g_scale0[PROJ], g_shift0[PROJ];
__device__ float g_sumH[MM],  g_ssqH[MM],  g_scaleH[MM],  g_shiftH[MM];
__device__ float g_h0[NG * M3];
__device__ float g_h1[NG * 768];
__device__ float g_h2[NG * MM];

// CSR scratch
__device__ int g_deg[2 * NN];
__device__ int g_off_in[NN + 1];
__device__ int g_off_out[NN + 1];
__device__ int g_cur[2 * NN];
__device__ int g_adj_in[NE];
__device__ int g_adj_out[NE];

// bf16 hi/lo weight scratch
__device__ __nv_bfloat16 g_wrt_hi[128 * 128], g_wrt_lo[128 * 128];   // w_root
__device__ __nv_bfloat16 g_wrl_hi[128 * 128], g_wrl_lo[128 * 128];   // w_rel
__device__ __nv_bfloat16 g_wl_hi[384 * 384],  g_wl_lo[384 * 384];    // lin_w

// bf16 hi/lo activation scratch
__device__ __nv_bfloat16 g_abuf_hi[(size_t)NN * CIN];  // x, then neigh (reused)
__device__ __nv_bfloat16 g_abuf_lo[(size_t)NN * CIN];
__device__ __nv_bfloat16 g_Hchi[(size_t)NN * MM];
__device__ __nv_bfloat16 g_Hclo[(size_t)NN * MM];

// ---------------- small helpers ---------------------------------------------
__device__ __forceinline__ uint32_t smem_u32(const void* p) {
    uint32_t a;
    asm("{ .reg .u64 t; cvta.to.shared.u64 t, %1; cvt.u32.u64 %0, t; }"
        : "=r"(a) : "l"(p));
    return a;
}
__device__ __forceinline__ void split_bf16(float v, __nv_bfloat16* hi, __nv_bfloat16* lo) {
    __nv_bfloat16 h = __float2bfloat16(v);
    *hi = h;
    *lo = __float2bfloat16(v - __bfloat162float(h));
}

__global__ void prep_w(const float* __restrict__ w_root, const float* __restrict__ w_rel,
                       const float* __restrict__ lin_w) {
    int i = blockIdx.x * blockDim.x + threadIdx.x;
    if (i < 128 * 128) {
        split_bf16(w_root[i], &g_wrt_hi[i], &g_wrt_lo[i]);
        split_bf16(w_rel[i],  &g_wrl_hi[i], &g_wrl_lo[i]);
    }
    if (i < 384 * 384) {
        split_bf16(lin_w[i], &g_wl_hi[i], &g_wl_lo[i]);
    }
}

// fp32 array -> bf16 hi/lo, vectorized by 4
__global__ void split_arr(const float* __restrict__ src,
                          __nv_bfloat16* __restrict__ hi,
                          __nv_bfloat16* __restrict__ lo, size_t n4) {
    size_t i  = (size_t)blockIdx.x * blockDim.x + threadIdx.x;
    size_t st = (size_t)gridDim.x * blockDim.x;
    for (; i < n4; i += st) {
        float4 v = ((const float4*)src)[i];
        __nv_bfloat16 h0, h1, h2, h3, l0, l1, l2, l3;
        split_bf16(v.x, &h0, &l0); split_bf16(v.y, &h1, &l1);
        split_bf16(v.z, &h2, &l2); split_bf16(v.w, &h3, &l3);
        ((__nv_bfloat162*)hi)[i * 2 + 0] = __nv_bfloat162(h0, h1);
        ((__nv_bfloat162*)hi)[i * 2 + 1] = __nv_bfloat162(h2, h3);
        ((__nv_bfloat162*)lo)[i * 2 + 0] = __nv_bfloat162(l0, l1);
        ((__nv_bfloat162*)lo)[i * 2 + 1] = __nv_bfloat162(l2, l3);
    }
}

// ================= HMMA GEMM (mma.sync bf16, hi/lo split, fp32 accum) =======
// C[row0:+128, col0:+128] = A[row0:+128, 0:K] @ W[col0:+128, 0:K]^T
// A and W both pre-split bf16 hi/lo, row-major. K consumed in 64-wide tiles.
#define SAB 144                        // SMEM row stride in bytes (64 bf16 + 16B pad)
#define HM_SMEM (4 * 128 * SAB)        // 73728 B: Ahi, Alo, Whi, Wlo

#define LDM_X4(r, a) \
    asm volatile("ldmatrix.sync.aligned.m8n8.x4.shared.b16 {%0,%1,%2,%3}, [%4];" \
                 : "=r"((r)[0]), "=r"((r)[1]), "=r"((r)[2]), "=r"((r)[3]) : "r"(a))
#define LDM_X2(r, a) \
    asm volatile("ldmatrix.sync.aligned.m8n8.x2.shared.b16 {%0,%1}, [%2];" \
                 : "=r"((r)[0]), "=r"((r)[1]) : "r"(a))
#define MMA16816(c, a, b) \
    asm volatile("mma.sync.aligned.m16n8k16.row.col.f32.bf16.bf16.f32 " \
                 "{%0,%1,%2,%3}, {%4,%5,%6,%7}, {%8,%9}, {%0,%1,%2,%3};" \
                 : "+f"((c)[0]), "+f"((c)[1]), "+f"((c)[2]), "+f"((c)[3]) \
                 : "r"((a)[0]), "r"((a)[1]), "r"((a)[2]), "r"((a)[3]), \
                   "r"((b)[0]), "r"((b)[1]))

__global__ void __launch_bounds__(256, 2)
hmma_gemm(const __nv_bfloat16* __restrict__ Ahi, const __nv_bfloat16* __restrict__ Alo,
          int lda,
          const __nv_bfloat16* __restrict__ Whi, const __nv_bfloat16* __restrict__ Wlo,
          int ktot, const float* __restrict__ bias,
          float* __restrict__ C, int ldc, int Nrows, int K0, int masked, int accumulate) {
    extern __shared__ char smem[];
    char* sAh = smem;
    char* sAl = smem + 128 * SAB;
    char* sWh = smem + 2 * 128 * SAB;
    char* sWl = smem + 3 * 128 * SAB;

    const int tid  = threadIdx.x;
    const int lane = tid & 31;
    const int warp = tid >> 5;
    const int wm   = warp >> 1;        // 0..3 (32-row strips)
    const int wn   = warp & 1;         // 0..1 (64-col strips)
    const int row0 = blockIdx.x * 128;
    const int cb   = masked ? blockIdx.y : 0;
    const int K    = masked ? 128 * (cb + 1) : K0;
    const int col0 = cb * 128;
    const int ntile = K >> 6;

    float acc[2][8][4];
#pragma unroll
    for (int mt = 0; mt < 2; mt++)
#pragma unroll
        for (int nt = 0; nt < 8; nt++)
#pragma unroll
            for (int j = 0; j < 4; j++) acc[mt][nt][j] = 0.f;

    const uint32_t bAh = smem_u32(sAh), bAl = smem_u32(sAl);
    const uint32_t bWh = smem_u32(sWh), bWl = smem_u32(sWl);
    const int aoff = (lane & 15) * SAB + (lane >> 4) * 16;       // A frag lane addr
    const int boff = (lane & 7) * SAB + ((lane >> 3) & 1) * 16;  // B frag lane addr
    const int cpr = tid >> 3, cpq = tid & 7;                     // copy row/quad

#pragma unroll 1
    for (int kt = 0; kt < ntile; kt++) {
        const int koff = kt * 64;
        __syncthreads();               // SMEM free to overwrite
        // ---- copy A (128x64) hi/lo and W (128x64) hi/lo, uint4 ----
        {
            const uint4 z = make_uint4(0, 0, 0, 0);
#pragma unroll
            for (int i = 0; i < 4; i++) {
                int r = cpr + i * 32;
                int gr = row0 + r;
                uint4 vh = z, vl = z;
                if (gr < Nrows) {
                    vh = ((const uint4*)(Ahi + (size_t)gr * lda + koff))[cpq];
                    vl = ((const uint4*)(Alo + (size_t)gr * lda + koff))[cpq];
                }
                *(uint4*)(sAh + r * SAB + cpq * 16) = vh;
                *(uint4*)(sAl + r * SAB + cpq * 16) = vl;
                uint4 wh = ((const uint4*)(Whi + (size_t)(col0 + r) * ktot + koff))[cpq];
                uint4 wl = ((const uint4*)(Wlo + (size_t)(col0 + r) * ktot + koff))[cpq];
                *(uint4*)(sWh + r * SAB + cpq * 16) = wh;
                *(uint4*)(sWl + r * SAB + cpq * 16) = wl;
            }
        }
        __syncthreads();

        // ---- 4 k-steps of 16 ----
#pragma unroll 1
        for (int ks = 0; ks < 4; ks++) {
            const int kb = ks * 32;    // byte offset of k-step
            uint32_t bh[8][2], bl[8][2];
#pragma unroll
            for (int nt = 0; nt < 8; nt++) {
                int n0 = (wn * 64 + nt * 8) * SAB + kb;
                LDM_X2(bh[nt], bWh + n0 + boff);
                LDM_X2(bl[nt], bWl + n0 + boff);
            }
#pragma unroll
            for (int mt = 0; mt < 2; mt++) {
                int r0 = (wm * 32 + mt * 16) * SAB + kb;
                uint32_t ah[4], al[4];
                LDM_X4(ah, bAh + r0 + aoff);
                LDM_X4(al, bAl + r0 + aoff);
#pragma unroll
                for (int nt = 0; nt < 8; nt++) {
                    MMA16816(acc[mt][nt], ah, bh[nt]);
                    MMA16816(acc[mt][nt], ah, bl[nt]);
                    MMA16816(acc[mt][nt], al, bh[nt]);
                }
            }
        }
    }

    // ---- epilogue ----
    const int g = lane >> 2, t = (lane & 3) * 2;
#pragma unroll
    for (int mt = 0; mt < 2; mt++) {
        int r1 = row0 + wm * 32 + mt * 16 + g;
        int r2 = r1 + 8;
#pragma unroll
        for (int nt = 0; nt < 8; nt++) {
            int cc = col0 + wn * 64 + nt * 8 + t;
            if (r1 < Nrows) {
                float* p = C + (size_t)r1 * ldc + cc;
                if (accumulate) { p[0] += acc[mt][nt][0]; p[1] += acc[mt][nt][1]; }
                else {
                    float b0 = bias ? bias[cc] : 0.f, b1 = bias ? bias[cc + 1] : 0.f;
                    p[0] = acc[mt][nt][0] + b0; p[1] = acc[mt][nt][1] + b1;
                }
            }
            if (r2 < Nrows) {
                float* p = C + (size_t)r2 * ldc + cc;
                if (accumulate) { p[0] += acc[mt][nt][2]; p[1] += acc[mt][nt][3]; }
                else {
                    float b0 = bias ? bias[cc] : 0.f, b1 = bias ? bias[cc + 1] : 0.f;
                    p[0] = acc[mt][nt][2] + b0; p[1] = acc[mt][nt][3] + b1;
                }
            }
        }
    }
}

// ---------------- misc helpers ----------------------------------------------
__device__ __forceinline__ void atomicMaxF(float* addr, float v) {
    if (v >= 0.f) atomicMax((int*)addr, __float_as_int(v));
    else          atomicMin((unsigned int*)addr, (unsigned int)__float_as_int(v));
}

__global__ void fill_f(float* p, size_t n, float v) {
    size_t i  = (size_t)blockIdx.x * blockDim.x + threadIdx.x;
    size_t st = (size_t)gridDim.x * blockDim.x;
    for (; i < n; i += st) p[i] = v;
}
__global__ void fill_i(int* p, size_t n, int v) {
    size_t i  = (size_t)blockIdx.x * blockDim.x + threadIdx.x;
    size_t st = (size_t)gridDim.x * blockDim.x;
    for (; i < n; i += st) p[i] = v;
}

// ---------------- CSR build --------------------------------------------------
__global__ void count_deg(const int* __restrict__ row, const int* __restrict__ col,
                          int E, int* deg_in, int* deg_out) {
    int e = blockIdx.x * blockDim.x + threadIdx.x;
    if (e >= E) return;
    atomicAdd(&deg_in[col[e]], 1);
    atomicAdd(&deg_out[row[e]], 1);
}

// warp-shuffle two-level exclusive scan (single block, 1024 threads)
__global__ void __launch_bounds__(1024)
exscan2c(const int* deg_in, int* off_in, const int* deg_out, int* off_out,
         int* cur, int n) {
    __shared__ int wsum[33];
    const int tid = threadIdx.x, lane = tid & 31, wid = tid >> 5;
    for (int pass = 0; pass < 2; pass++) {
        const int* deg = pass ? deg_out : deg_in;
        int*       off = pass ? off_out : off_in;
        int*       cu  = pass ? cur + n : cur;
        int carry = 0;
        for (int base = 0; base < n; base += 1024) {
            int i = base + tid;
            int v = (i < n) ? deg[i] : 0;
            int incl = v;
#pragma unroll
            for (int o = 1; o < 32; o <<= 1) {
                int t = __shfl_up_sync(0xFFFFFFFFu, incl, o);
                if (lane >= o) incl += t;
            }
            if (lane == 31) wsum[wid] = incl;
            __syncthreads();
            if (wid == 0) {
                int s = wsum[lane];
                int is = s;
#pragma unroll
                for (int o = 1; o < 32; o <<= 1) {
                    int t = __shfl_up_sync(0xFFFFFFFFu, is, o);
                    if (lane >= o) is += t;
                }
                wsum[lane] = is - s;
                if (lane == 31) wsum[32] = is;
            }
            __syncthreads();
            int excl = carry + wsum[wid] + incl - v;
            if (i < n) { off[i] = excl; cu[i] = excl; }
            carry += wsum[32];
            __syncthreads();
        }
        if (tid == 0) off[n] = carry;
        __syncthreads();
    }
}

__global__ void build_lists(const int* __restrict__ row, const int* __restrict__ col,
                            int E, int* cur, int* adj_in, int* adj_out, int n) {
    int e = blockIdx.x * blockDim.x + threadIdx.x;
    if (e >= E) return;
    int r = row[e], c = col[e];
    int p1 = atomicAdd(&cur[c], 1);
    adj_in[p1] = r;
    int p2 = atomicAdd(&cur[n + r], 1);
    adj_out[p2] = c;
}

// ---------------- gather SpMM (optional fp32 out, optional bf16 hi/lo out) --
__global__ void __launch_bounds__(256)
gather_spmm(const float* __restrict__ src, int lds,
            float* dst, int ldd,
            __nv_bfloat16* hi, __nv_bfloat16* lo, int ldh,
            const int* __restrict__ off, const int* __restrict__ adj, int N) {
    int node = blockIdx.x * blockDim.y + threadIdx.y;
    if (node >= N) return;
    int s = off[node], e = off[node + 1];
    int lane = threadIdx.x;
    float4 acc0 = make_float4(0.f, 0.f, 0.f, 0.f);
    float4 acc1 = make_float4(0.f, 0.f, 0.f, 0.f);
    int i = s;
    for (; i + 1 < e; i += 2) {
        int sr0 = __ldg(&adj[i]);
        int sr1 = __ldg(&adj[i + 1]);
        float4 v0 = *(const float4*)(src + (size_t)sr0 * lds + lane * 4);
        float4 v1 = *(const float4*)(src + (size_t)sr1 * lds + lane * 4);
        acc0.x += v0.x; acc0.y += v0.y; acc0.z += v0.z; acc0.w += v0.w;
        acc1.x += v1.x; acc1.y += v1.y; acc1.z += v1.z; acc1.w += v1.w;
    }
    if (i < e) {
        int sr = __ldg(&adj[i]);
        float4 v = *(const float4*)(src + (size_t)sr * lds + lane * 4);
        acc0.x += v.x; acc0.y += v.y; acc0.z += v.z; acc0.w += v.w;
    }
    acc0.x += acc1.x; acc0.y += acc1.y; acc0.z += acc1.z; acc0.w += acc1.w;
    if (dst)
        *(float4*)(dst + (size_t)node * ldd + lane * 4) = acc0;
    if (hi) {
        __nv_bfloat16 h0, h1, h2, h3, l0, l1, l2, l3;
        split_bf16(acc0.x, &h0, &l0); split_bf16(acc0.y, &h1, &l1);
        split_bf16(acc0.z, &h2, &l2); split_bf16(acc0.w, &h3, &l3);
        size_t o = (size_t)node * ldh + lane * 4;
        *(__nv_bfloat162*)(hi + o)     = __nv_bfloat162(h0, h1);
        *(__nv_bfloat162*)(hi + o + 2) = __nv_bfloat162(h2, h3);
        *(__nv_bfloat162*)(lo + o)     = __nv_bfloat162(l0, l1);
        *(__nv_bfloat162*)(lo + o + 2) = __nv_bfloat162(l2, l3);
    }
}

// ---------------- BN stats / apply ------------------------------------------
__global__ void colstats(const float* __restrict__ A, int lda, int N,
                         float* sum, float* ssq) {
    int c = threadIdx.x;
    float s = 0.f, q = 0.f;
    for (int r = blockIdx.x; r < N; r += gridDim.x) {
        float v = A[(size_t)r * lda + c];
        s += v;
        q += v * v;
    }
    atomicAdd(&sum[c], s);
    atomicAdd(&ssq[c], q);
}

__global__ void mkaffine(const float* sum, const float* ssq,
                         const float* g, const float* b,
                         float* scale, float* shift, int C, float invN) {
    int c = blockIdx.x * blockDim.x + threadIdx.x;
    if (c >= C) return;
    float m  = sum[c] * invN;
    float v  = fmaxf(ssq[c] * invN - m * m, 0.f);
    float sc = g[c] * rsqrtf(v + EPSV);
    scale[c] = sc;
    shift[c] = b[c] - m * sc;
}

// BN-apply on 128-col slab of 384-stride Hc + write bf16 hi/lo split
__global__ void applybn_split(float* A, int lda, int N,
                              const float* __restrict__ scale,
                              const float* __restrict__ shift,
                              __nv_bfloat16* hi, __nv_bfloat16* lo) {
    size_t total = (size_t)N * 32;      // 32 float4s per row
    size_t i  = (size_t)blockIdx.x * blockDim.x + threadIdx.x;
    size_t st = (size_t)gridDim.x * blockDim.x;
    for (; i < total; i += st) {
        int r = (int)(i >> 5), c4 = (int)(i & 31) * 4;
        float* p = A + (size_t)r * lda + c4;
        float4 v = *(float4*)p;
        v.x = fmaf(v.x, scale[c4 + 0], shift[c4 + 0]);
        v.y = fmaf(v.y, scale[c4 + 1], shift[c4 + 1]);
        v.z = fmaf(v.z, scale[c4 + 2], shift[c4 + 2]);
        v.w = fmaf(v.w, scale[c4 + 3], shift[c4 + 3]);
        *(float4*)p = v;
        __nv_bfloat16 h0, h1, h2, h3, l0, l1, l2, l3;
        split_bf16(v.x, &h0, &l0); split_bf16(v.y, &h1, &l1);
        split_bf16(v.z, &h2, &l2); split_bf16(v.w, &h3, &l3);
        size_t o = (size_t)r * lda + c4;
        *(__nv_bfloat162*)(hi + o)     = __nv_bfloat162(h0, h1);
        *(__nv_bfloat162*)(hi + o + 2) = __nv_bfloat162(h2, h3);
        *(__nv_bfloat162*)(lo + o)     = __nv_bfloat162(l0, l1);
        *(__nv_bfloat162*)(lo + o + 2) = __nv_bfloat162(l2, l3);
    }
}

// ---------------- fused BN-apply + segment add/max pooling ------------------
#define POOL_NPB 64
__global__ void __launch_bounds__(384)
pool_kernel(const float* __restrict__ Hm,
            const float* __restrict__ scale, const float* __restrict__ shift,
            const int* __restrict__ batch, int N,
            float* Hadd, float* Hmax, float* cnt) {
    __shared__ int sb[POOL_NPB];
    int c  = threadIdx.x;
    int n0 = blockIdx.x * POOL_NPB;
    int nEnd = min(n0 + POOL_NPB, N);
    if (c < POOL_NPB && n0 + c < N) sb[c] = batch[n0 + c];
    __syncthreads();

    float sc = scale[c], sh = shift[c];
    float accA = 0.f, accM = -INFINITY, accC = 0.f;
    int curg = -1;
    for (int n = n0; n < nEnd; n++) {
        int g = sb[n - n0];
        if (g != curg) {
            if (curg >= 0) {
                atomicAdd(&Hadd[(size_t)curg * MM + c], accA);
                atomicMaxF(&Hmax[(size_t)curg * MM + c], accM);
                if (c == 0) atomicAdd(&cnt[curg], accC);
            }
            accA = 0.f; accM = -INFINITY; accC = 0.f; curg = g;
        }
        float v = fmaf(Hm[(size_t)n * MM + c], sc, sh);
        accA += v;
        accM = fmaxf(accM, v);
        accC += 1.f;
    }
    if (curg >= 0) {
        atomicAdd(&Hadd[(size_t)curg * MM + c], accA);
        atomicMaxF(&Hmax[(size_t)curg * MM + c], accM);
        if (c == 0) atomicAdd(&cnt[curg], accC);
    }
}

// ---------------- BN over graphs --------------------------------------------
__global__ void bn_graphs(const float* __restrict__ Hadd,
                          const float* __restrict__ Hmax,
                          const float* __restrict__ cnt,
                          const float* __restrict__ g,
                          const float* __restrict__ b,
                          float* __restrict__ h0) {
    int col = blockIdx.x;
    int t   = threadIdx.x;
    float v;
    if (col < MM) {
        v = Hadd[(size_t)t * MM + col] / fmaxf(cnt[t], 1.f);
    } else if (col < 2 * MM) {
        v = Hadd[(size_t)t * MM + (col - MM)];
    } else {
        v = Hmax[(size_t)t * MM + (col - 2 * MM)];
        if (!isfinite(v)) v = 0.f;
    }
    __shared__ float s1[128], s2[128];
    s1[t] = v; s2[t] = v * v;
    __syncthreads();
    for (int o = 64; o > 0; o >>= 1) {
        if (t < o) { s1[t] += s1[t + o]; s2[t] += s2[t + o]; }
        __syncthreads();
    }
    float m   = s1[0] * (1.f / 128.f);
    float var = fmaxf(s2[0] * (1.f / 128.f) - m * m, 0.f);
    h0[(size_t)t * M3 + col] = (v - m) * rsqrtf(var + EPSV) * g[col] + b[col];
}

// ---------------- tiny MLP layers -------------------------------------------
__global__ void mlp_layer(const float* __restrict__ X, int ldx,
                          const float* __restrict__ W, int ldw,
                          const float* __restrict__ bias,
                          float* __restrict__ Y, int ldy, int K, int doRelu) {
    int o = blockIdx.x;
    int gI = threadIdx.x;
    const float* w  = W + (size_t)o * ldw;
    const float* xr = X + (size_t)gI * ldx;
    float acc = 0.f;
    for (int k = 0; k < K; k++) acc = fmaf(xr[k], __ldg(&w[k]), acc);
    acc += bias[o];
    if (doRelu) acc = fmaxf(acc, 0.f);
    Y[(size_t)gI * ldy + o] = acc;
}

__global__ void head_kernel(const float* __restrict__ h2,
                            const float* __restrict__ w3,
                            const float* __restrict__ b3,
                            float* __restrict__ out) {
    int gI = threadIdx.x;
    float l0 = b3[0], l1 = b3[1];
    const float* xr = h2 + (size_t)gI * MM;
    for (int k = 0; k < MM; k++) {
        float x = xr[k];
        l0 = fmaf(x, __ldg(&w3[k]), l0);
        l1 = fmaf(x, __ldg(&w3[MM + k]), l1);
    }
    float mx  = fmaxf(l0, l1);
    float lse = mx + logf(expf(l0 - mx) + expf(l1 - mx));
    out[gI * 2 + 0] = l0 - lse;
    out[gI * 2 + 1] = l1 - lse;
}

// ---------------- launcher ---------------------------------------------------
extern "C" void kernel_launch(void* const* d_in, const int* in_sizes, int n_in,
                              void* d_out, int out_size) {
    const float* x       = (const float*)d_in[0];
    const int*   eidx    = (const int*)d_in[1];
    const int*   batch   = (const int*)d_in[2];
    const float* w_rel   = (const float*)d_in[4];
    const float* b_rel   = (const float*)d_in[5];
    const float* w_root  = (const float*)d_in[6];
    const float* norm0_g = (const float*)d_in[7];
    const float* norm0_b = (const float*)d_in[8];
    const float* lin_w   = (const float*)d_in[9];
    const float* lin_b   = (const float*)d_in[10];
    const float* bnh_g   = (const float*)d_in[11];
    const float* bnh_b   = (const float*)d_in[12];
    const float* bno_g   = (const float*)d_in[13];
    const float* bno_b   = (const float*)d_in[14];
    const float* w1      = (const float*)d_in[15];
    const float* b1      = (const float*)d_in[16];
    const float* w2      = (const float*)d_in[17];
    const float* b2      = (const float*)d_in[18];
    const float* w3      = (const float*)d_in[19];
    const float* b3      = (const float*)d_in[20];
    float* out = (float*)d_out;

    const int* row = eidx;
    const int* col = eidx + NE;

    float *Hc, *Hm, *Hadd, *Hmax, *cnt;
    float *sum0, *ssq0, *scale0, *shift0, *sumH, *ssqH, *scaleH, *shiftH;
    float *h0, *h1, *h2;
    int *deg, *off_in, *off_out, *cur, *adj_in, *adj_out;
    __nv_bfloat16 *wrt_hi, *wrt_lo, *wrl_hi, *wrl_lo, *wl_hi, *wl_lo;
    __nv_bfloat16 *abuf_hi, *abuf_lo, *Hchi, *Hclo;
    cudaGetSymbolAddress((void**)&Hc,     g_Hc);
    cudaGetSymbolAddress((void**)&Hm,     g_Hm);
    cudaGetSymbolAddress((void**)&Hadd,   g_Hadd);
    cudaGetSymbolAddress((void**)&Hmax,   g_Hmax);
    cudaGetSymbolAddress((void**)&cnt,    g_cnt);
    cudaGetSymbolAddress((void**)&sum0,   g_sum0);
    cudaGetSymbolAddress((void**)&ssq0,   g_ssq0);
    cudaGetSymbolAddress((void**)&scale0, g_scale0);
    cudaGetSymbolAddress((void**)&shift0, g_shift0);
    cudaGetSymbolAddress((void**)&sumH,   g_sumH);
    cudaGetSymbolAddress((void**)&ssqH,   g_ssqH);
    cudaGetSymbolAddress((void**)&scaleH, g_scaleH);
    cudaGetSymbolAddress((void**)&shiftH, g_shiftH);
    cudaGetSymbolAddress((void**)&h0,     g_h0);
    cudaGetSymbolAddress((void**)&h1,     g_h1);
    cudaGetSymbolAddress((void**)&h2,     g_h2);
    cudaGetSymbolAddress((void**)&deg,     g_deg);
    cudaGetSymbolAddress((void**)&off_in,  g_off_in);
    cudaGetSymbolAddress((void**)&off_out, g_off_out);
    cudaGetSymbolAddress((void**)&cur,     g_cur);
    cudaGetSymbolAddress((void**)&adj_in,  g_adj_in);
    cudaGetSymbolAddress((void**)&adj_out, g_adj_out);
    cudaGetSymbolAddress((void**)&wrt_hi,  g_wrt_hi);
    cudaGetSymbolAddress((void**)&wrt_lo,  g_wrt_lo);
    cudaGetSymbolAddress((void**)&wrl_hi,  g_wrl_hi);
    cudaGetSymbolAddress((void**)&wrl_lo,  g_wrl_lo);
    cudaGetSymbolAddress((void**)&wl_hi,   g_wl_hi);
    cudaGetSymbolAddress((void**)&wl_lo,   g_wl_lo);
    cudaGetSymbolAddress((void**)&abuf_hi, g_abuf_hi);
    cudaGetSymbolAddress((void**)&abuf_lo, g_abuf_lo);
    cudaGetSymbolAddress((void**)&Hchi,    g_Hchi);
    cudaGetSymbolAddress((void**)&Hclo,    g_Hclo);

    cudaFuncSetAttribute(hmma_gemm, cudaFuncAttributeMaxDynamicSharedMemorySize, HM_SMEM);

    int ggrid = (NN + 127) / 128;        // 391 row blocks
    dim3 gblk(32, 8);
    int ggrid_n = (NN + 7) / 8;

    // #1..#3
    fill_i<<<256, 256>>>(deg, (size_t)2 * NN, 0);
    prep_w<<<(384 * 384 + 255) / 256, 256>>>(w_root, w_rel, lin_w);
    split_arr<<<1024, 256>>>(x, abuf_hi, abuf_lo, (size_t)NN * CIN / 4);

    // #4 (ncu-profiled): Hc[:,0:128] = x @ w_root^T + b_rel
    hmma_gemm<<<dim3(ggrid, 1), 256, HM_SMEM>>>(
        abuf_hi, abuf_lo, CIN, wrt_hi, wrt_lo, 128, b_rel, Hc, MM, NN, 128, 0, 0);

    // CSR build + GraphConv gather (writes bf16 hi/lo only; reuses abuf)
    count_deg<<<(NE + 255) / 256, 256>>>(row, col, NE, deg, deg + NN);
    exscan2c<<<1, 1024>>>(deg, off_in, deg + NN, off_out, cur, NN);
    build_lists<<<(NE + 255) / 256, 256>>>(row, col, NE, cur, adj_in, adj_out, NN);
    gather_spmm<<<ggrid_n, gblk>>>(x, CIN, nullptr, 0, abuf_hi, abuf_lo, CIN,
                                   off_in, adj_in, NN);

    // Hc[:,0:128] += neigh @ w_rel^T
    hmma_gemm<<<dim3(ggrid, 1), 256, HM_SMEM>>>(
        abuf_hi, abuf_lo, CIN, wrl_hi, wrl_lo, 128, nullptr, Hc, MM, NN, 128, 0, 1);

    // BN0 stats + apply in place (+ bf16 split of X block)
    fill_f<<<1, 256>>>(sum0, (size_t)PROJ, 0.f);
    fill_f<<<1, 256>>>(ssq0, (size_t)PROJ, 0.f);
    colstats<<<512, PROJ>>>(Hc, MM, NN, sum0, ssq0);
    mkaffine<<<1, PROJ>>>(sum0, ssq0, norm0_g, norm0_b, scale0, shift0, PROJ, 1.f / NN);
    applybn_split<<<2048, 256>>>(Hc, MM, NN, scale0, shift0, Hchi, Hclo);

    // k-hop diffusion: H1 (fp32 + split), H2 (split only)
    gather_spmm<<<ggrid_n, gblk>>>(Hc, MM, Hc + PROJ, MM, Hchi + PROJ, Hclo + PROJ, MM,
                                   off_out, adj_out, NN);
    gather_spmm<<<ggrid_n, gblk>>>(Hc + PROJ, MM, nullptr, 0, Hchi + 2 * PROJ, Hclo + 2 * PROJ, MM,
                                   off_out, adj_out, NN);

    // masked lin: 3 col-blocks, K = 128*(y+1)
    hmma_gemm<<<dim3(ggrid, 3), 256, HM_SMEM>>>(
        Hchi, Hclo, MM, wl_hi, wl_lo, MM, lin_b, Hm, MM, NN, 128, 1, 0);

    // BN over nodes (stats only; affine fused into pooling)
    fill_f<<<2, 256>>>(sumH, (size_t)MM, 0.f);
    fill_f<<<2, 256>>>(ssqH, (size_t)MM, 0.f);
    colstats<<<512, MM>>>(Hm, MM, NN, sumH, ssqH);
    mkaffine<<<2, 256>>>(sumH, ssqH, bnh_g, bnh_b, scaleH, shiftH, MM, 1.f / NN);

    // pooling
    fill_f<<<64, 256>>>(Hadd, (size_t)NG * MM, 0.f);
    fill_f<<<64, 256>>>(Hmax, (size_t)NG * MM, -INFINITY);
    fill_f<<<1, 128>>>(cnt, (size_t)NG, 0.f);
    pool_kernel<<<(NN + POOL_NPB - 1) / POOL_NPB, 384>>>(
        Hm, scaleH, shiftH, batch, NN, Hadd, Hmax, cnt);

    // graph BN + funnel MLP + log_softmax
    bn_graphs<<<M3, 128>>>(Hadd, Hmax, cnt, bno_g, bno_b, h0);
    mlp_layer<<<768, 128>>>(h0, M3, w1, M3, b1, h1, 768, M3, 1);
    mlp_layer<<<MM, 128>>>(h1, 768, w2, 768, b2, h2, MM, 768, 1);
    head_kernel<<<1, 128>>>(h2, w3, b3, out);
}

// round 17
// speedup vs baseline: 2.8315x; 1.8346x over previous
#include <cuda_runtime.h>
#include <cuda_bf16.h>
#include <math.h>
#include <stdint.h>

// Problem constants (fixed by the dataset)
#define NN   50000
#define NE   600000
#define NG   128
#define CIN  128
#define PROJ 128
#define MM   384          // OUT_CH * K
#define M3   1152         // 3 * MM
#define EPSV 1e-5f

// ---------------- scratch (static device globals; no allocation allowed) ---
__device__ float g_Hc[(size_t)NN * MM];         // [X | H1 | H2] fp32
__device__ float g_Hm[(size_t)NN * MM];         // pre-BN hidden
__device__ float g_Hadd[NG * MM];
__device__ float g_Hmax[NG * MM];
__device__ float g_cnt[NG];
__device__ float g_sum0[PROJ], g_ssq0[PROJ], g_scale0[PROJ], g_shift0[PROJ];
__device__ float g_sumH[MM],  g_ssqH[MM],  g_scaleH[MM],  g_shiftH[MM];
__device__ float g_h0[NG * M3];     // transposed: [col][graph]
__device__ float g_h1[NG * 768];    // transposed: [o][graph]
__device__ float g_h2[NG * MM];     // transposed: [o][graph]

// CSR scratch
__device__ int g_deg[2 * NN];
__device__ int g_off_in[NN + 1];
__device__ int g_off_out[NN + 1];
__device__ int g_cur[2 * NN];
__device__ int g_adj_in[NE];
__device__ int g_adj_out[NE];

// bf16 hi/lo weight scratch
__device__ __nv_bfloat16 g_wrt_hi[128 * 128], g_wrt_lo[128 * 128];   // w_root
__device__ __nv_bfloat16 g_wrl_hi[128 * 128], g_wrl_lo[128 * 128];   // w_rel
__device__ __nv_bfloat16 g_wl_hi[384 * 384],  g_wl_lo[384 * 384];    // lin_w

// bf16 hi/lo activation scratch
__device__ __nv_bfloat16 g_abuf_hi[(size_t)NN * CIN];  // x, then neigh (reused)
__device__ __nv_bfloat16 g_abuf_lo[(size_t)NN * CIN];
__device__ __nv_bfloat16 g_Hchi[(size_t)NN * MM];
__device__ __nv_bfloat16 g_Hclo[(size_t)NN * MM];

// ---------------- small helpers ---------------------------------------------
__device__ __forceinline__ uint32_t smem_u32(const void* p) {
    uint32_t a;
    asm("{ .reg .u64 t; cvta.to.shared.u64 t, %1; cvt.u32.u64 %0, t; }"
        : "=r"(a) : "l"(p));
    return a;
}
__device__ __forceinline__ void split_bf16(float v, __nv_bfloat16* hi, __nv_bfloat16* lo) {
    __nv_bfloat16 h = __float2bfloat16(v);
    *hi = h;
    *lo = __float2bfloat16(v - __bfloat162float(h));
}

__global__ void prep_w(const float* __restrict__ w_root, const float* __restrict__ w_rel,
                       const float* __restrict__ lin_w) {
    int i = blockIdx.x * blockDim.x + threadIdx.x;
    if (i < 128 * 128) {
        split_bf16(w_root[i], &g_wrt_hi[i], &g_wrt_lo[i]);
        split_bf16(w_rel[i],  &g_wrl_hi[i], &g_wrl_lo[i]);
    }
    if (i < 384 * 384) {
        split_bf16(lin_w[i], &g_wl_hi[i], &g_wl_lo[i]);
    }
}

// fp32 array -> bf16 hi/lo, vectorized by 4
__global__ void split_arr(const float* __restrict__ src,
                          __nv_bfloat16* __restrict__ hi,
                          __nv_bfloat16* __restrict__ lo, size_t n4) {
    size_t i  = (size_t)blockIdx.x * blockDim.x + threadIdx.x;
    size_t st = (size_t)gridDim.x * blockDim.x;
    for (; i < n4; i += st) {
        float4 v = ((const float4*)src)[i];
        __nv_bfloat16 h0, h1, h2, h3, l0, l1, l2, l3;
        split_bf16(v.x, &h0, &l0); split_bf16(v.y, &h1, &l1);
        split_bf16(v.z, &h2, &l2); split_bf16(v.w, &h3, &l3);
        ((__nv_bfloat162*)hi)[i * 2 + 0] = __nv_bfloat162(h0, h1);
        ((__nv_bfloat162*)hi)[i * 2 + 1] = __nv_bfloat162(h2, h3);
        ((__nv_bfloat162*)lo)[i * 2 + 0] = __nv_bfloat162(l0, l1);
        ((__nv_bfloat162*)lo)[i * 2 + 1] = __nv_bfloat162(l2, l3);
    }
}

// ================= HMMA GEMM: cp.async double-buffered pipeline =============
// C[row0:+128, col0:+128] = A[row0:+128, 0:K] @ W[col0:+128, 0:K]^T
// A/W pre-split bf16 hi/lo row-major. K consumed in 32-wide tiles, 2 stages.
#define KT   32                          // k-tile in elements
#define SAB  80                          // SMEM row stride bytes (64 + 16 pad)
#define BUFB (128 * SAB)                 // one buffer (10240 B)
#define STAGEB (4 * BUFB)                // Ahi|Alo|Whi|Wlo per stage (40960 B)
#define HM_SMEM (2 * STAGEB)             // 81920 B

#define LDM_X4(r, a) \
    asm volatile("ldmatrix.sync.aligned.m8n8.x4.shared.b16 {%0,%1,%2,%3}, [%4];" \
                 : "=r"((r)[0]), "=r"((r)[1]), "=r"((r)[2]), "=r"((r)[3]) : "r"(a))
#define LDM_X2(r, a) \
    asm volatile("ldmatrix.sync.aligned.m8n8.x2.shared.b16 {%0,%1}, [%2];" \
                 : "=r"((r)[0]), "=r"((r)[1]) : "r"(a))
#define MMA16816(c, a, b) \
    asm volatile("mma.sync.aligned.m16n8k16.row.col.f32.bf16.bf16.f32 " \
                 "{%0,%1,%2,%3}, {%4,%5,%6,%7}, {%8,%9}, {%0,%1,%2,%3};" \
                 : "+f"((c)[0]), "+f"((c)[1]), "+f"((c)[2]), "+f"((c)[3]) \
                 : "r"((a)[0]), "r"((a)[1]), "r"((a)[2]), "r"((a)[3]), \
                   "r"((b)[0]), "r"((b)[1]))
#define CP16(sa, gp, sz) \
    asm volatile("cp.async.cg.shared.global [%0], [%1], 16, %2;" \
                 :: "r"(sa), "l"(gp), "r"(sz))
#define CP_COMMIT() asm volatile("cp.async.commit_group;")
#define CP_WAIT(N)  asm volatile("cp.async.wait_group %0;" :: "n"(N))

__global__ void __launch_bounds__(256, 2)
hmma_gemm(const __nv_bfloat16* __restrict__ Ahi, const __nv_bfloat16* __restrict__ Alo,
          int lda,
          const __nv_bfloat16* __restrict__ Whi, const __nv_bfloat16* __restrict__ Wlo,
          int ktot, const float* __restrict__ bias,
          float* __restrict__ C, int ldc, int Nrows, int K0, int masked, int accumulate) {
    extern __shared__ char smem[];

    const int tid  = threadIdx.x;
    const int lane = tid & 31;
    const int warp = tid >> 5;
    const int wm   = warp >> 1;        // 0..3 (32-row strips)
    const int wn   = warp & 1;         // 0..1 (64-col strips)
    const int row0 = blockIdx.x * 128;
    const int cb   = masked ? blockIdx.y : 0;
    const int K    = masked ? 128 * (cb + 1) : K0;
    const int col0 = cb * 128;
    const int ntile = K / KT;

    // per-thread copy assignment: row r, two 16B quads
    const int cr = tid >> 1;               // 0..127
    const int cq = (tid & 1) * 2;          // 0 or 2
    const int grow = row0 + cr;
    const unsigned asz = (grow < Nrows) ? 16u : 0u;
    const __nv_bfloat16* gAh = Ahi + (size_t)(grow < Nrows ? grow : 0) * lda;
    const __nv_bfloat16* gAl = Alo + (size_t)(grow < Nrows ? grow : 0) * lda;
    const __nv_bfloat16* gWh = Whi + (size_t)(col0 + cr) * ktot;
    const __nv_bfloat16* gWl = Wlo + (size_t)(col0 + cr) * ktot;
    const uint32_t srow = smem_u32(smem) + cr * SAB;

    float acc[2][8][4];
#pragma unroll
    for (int mt = 0; mt < 2; mt++)
#pragma unroll
        for (int nt = 0; nt < 8; nt++)
#pragma unroll
            for (int j = 0; j < 4; j++) acc[mt][nt][j] = 0.f;

    const int aoff = (lane & 15) * SAB + (lane >> 4) * 16;
    const int boff = (lane & 7) * SAB + ((lane >> 3) & 1) * 16;
    const uint32_t sbase = smem_u32(smem);

    // prefetch tile 0 into stage 0
    {
#pragma unroll
        for (int q = 0; q < 2; q++) {
            int qq = cq + q;
            CP16(srow + 0 * BUFB + qq * 16, gAh + qq * 8, asz);
            CP16(srow + 1 * BUFB + qq * 16, gAl + qq * 8, asz);
            CP16(srow + 2 * BUFB + qq * 16, gWh + qq * 8, 16u);
            CP16(srow + 3 * BUFB + qq * 16, gWl + qq * 8, 16u);
        }
        CP_COMMIT();
    }

#pragma unroll 1
    for (int kt = 0; kt < ntile; kt++) {
        // prefetch next tile into other stage
        if (kt + 1 < ntile) {
            const int ko = (kt + 1) * KT;
            const uint32_t sst = srow + ((kt + 1) & 1) * STAGEB;
#pragma unroll
            for (int q = 0; q < 2; q++) {
                int qq = cq + q;
                CP16(sst + 0 * BUFB + qq * 16, gAh + ko + qq * 8, asz);
                CP16(sst + 1 * BUFB + qq * 16, gAl + ko + qq * 8, asz);
                CP16(sst + 2 * BUFB + qq * 16, gWh + ko + qq * 8, 16u);
                CP16(sst + 3 * BUFB + qq * 16, gWl + ko + qq * 8, 16u);
            }
            CP_COMMIT();
            CP_WAIT(1);
        } else {
            CP_WAIT(0);
        }
        __syncthreads();

        const uint32_t st = sbase + (kt & 1) * STAGEB;
        const uint32_t bAh = st, bAl = st + BUFB, bWh = st + 2 * BUFB, bWl = st + 3 * BUFB;

        // 2 k-steps of 16 per tile
#pragma unroll
        for (int ks = 0; ks < 2; ks++) {
            const int kb = ks * 32;    // byte offset
            uint32_t bh[8][2], bl[8][2];
#pragma unroll
            for (int nt = 0; nt < 8; nt++) {
                int n0 = (wn * 64 + nt * 8) * SAB + kb;
                LDM_X2(bh[nt], bWh + n0 + boff);
                LDM_X2(bl[nt], bWl + n0 + boff);
            }
#pragma unroll
            for (int mt = 0; mt < 2; mt++) {
                int r0 = (wm * 32 + mt * 16) * SAB + kb;
                uint32_t ah[4], al[4];
                LDM_X4(ah, bAh + r0 + aoff);
                LDM_X4(al, bAl + r0 + aoff);
#pragma unroll
                for (int nt = 0; nt < 8; nt++) {
                    MMA16816(acc[mt][nt], ah, bh[nt]);
                    MMA16816(acc[mt][nt], ah, bl[nt]);
                    MMA16816(acc[mt][nt], al, bh[nt]);
                }
            }
        }
        __syncthreads();               // stage free before overwrite
    }

    // ---- epilogue ----
    const int g = lane >> 2, t = (lane & 3) * 2;
#pragma unroll
    for (int mt = 0; mt < 2; mt++) {
        int r1 = row0 + wm * 32 + mt * 16 + g;
        int r2 = r1 + 8;
#pragma unroll
        for (int nt = 0; nt < 8; nt++) {
            int cc = col0 + wn * 64 + nt * 8 + t;
            if (r1 < Nrows) {
                float* p = C + (size_t)r1 * ldc + cc;
                if (accumulate) { p[0] += acc[mt][nt][0]; p[1] += acc[mt][nt][1]; }
                else {
                    float b0 = bias ? bias[cc] : 0.f, b1 = bias ? bias[cc + 1] : 0.f;
                    p[0] = acc[mt][nt][0] + b0; p[1] = acc[mt][nt][1] + b1;
                }
            }
            if (r2 < Nrows) {
                float* p = C + (size_t)r2 * ldc + cc;
                if (accumulate) { p[0] += acc[mt][nt][2]; p[1] += acc[mt][nt][3]; }
                else {
                    float b0 = bias ? bias[cc] : 0.f, b1 = bias ? bias[cc + 1] : 0.f;
                    p[0] = acc[mt][nt][2] + b0; p[1] = acc[mt][nt][3] + b1;
                }
            }
        }
    }
}

// ---------------- misc helpers ----------------------------------------------
__device__ __forceinline__ void atomicMaxF(float* addr, float v) {
    if (v >= 0.f) atomicMax((int*)addr, __float_as_int(v));
    else          atomicMin((unsigned int*)addr, (unsigned int)__float_as_int(v));
}

__global__ void fill_i(int* p, size_t n, int v) {
    size_t i  = (size_t)blockIdx.x * blockDim.x + threadIdx.x;
    size_t st = (size_t)gridDim.x * blockDim.x;
    for (; i < n; i += st) p[i] = v;
}

// one launch to init all the small scratch arrays
__global__ void init_misc(float* Hadd, float* Hmax, float* cnt,
                          float* sum0, float* ssq0, float* sumH, float* ssqH) {
    int i = blockIdx.x * blockDim.x + threadIdx.x;
    if (i < NG * MM) { Hadd[i] = 0.f; Hmax[i] = -INFINITY; }
    if (i < NG) cnt[i] = 0.f;
    if (i < PROJ) { sum0[i] = 0.f; ssq0[i] = 0.f; }
    if (i < MM) { sumH[i] = 0.f; ssqH[i] = 0.f; }
}

// ---------------- CSR build --------------------------------------------------
__global__ void count_deg(const int* __restrict__ row, const int* __restrict__ col,
                          int E, int* deg_in, int* deg_out) {
    int e = blockIdx.x * blockDim.x + threadIdx.x;
    if (e >= E) return;
    atomicAdd(&deg_in[col[e]], 1);
    atomicAdd(&deg_out[row[e]], 1);
}

// warp-shuffle two-level exclusive scan (single block, 1024 threads)
__global__ void __launch_bounds__(1024)
exscan2c(const int* deg_in, int* off_in, const int* deg_out, int* off_out,
         int* cur, int n) {
    __shared__ int wsum[33];
    const int tid = threadIdx.x, lane = tid & 31, wid = tid >> 5;
    for (int pass = 0; pass < 2; pass++) {
        const int* deg = pass ? deg_out : deg_in;
        int*       off = pass ? off_out : off_in;
        int*       cu  = pass ? cur + n : cur;
        int carry = 0;
        for (int base = 0; base < n; base += 1024) {
            int i = base + tid;
            int v = (i < n) ? deg[i] : 0;
            int incl = v;
#pragma unroll
            for (int o = 1; o < 32; o <<= 1) {
                int t = __shfl_up_sync(0xFFFFFFFFu, incl, o);
                if (lane >= o) incl += t;
            }
            if (lane == 31) wsum[wid] = incl;
            __syncthreads();
            if (wid == 0) {
                int s = wsum[lane];
                int is = s;
#pragma unroll
                for (int o = 1; o < 32; o <<= 1) {
                    int t = __shfl_up_sync(0xFFFFFFFFu, is, o);
                    if (lane >= o) is += t;
                }
                wsum[lane] = is - s;
                if (lane == 31) wsum[32] = is;
            }
            __syncthreads();
            int excl = carry + wsum[wid] + incl - v;
            if (i < n) { off[i] = excl; cu[i] = excl; }
            carry += wsum[32];
            __syncthreads();
        }
        if (tid == 0) off[n] = carry;
        __syncthreads();
    }
}

__global__ void build_lists(const int* __restrict__ row, const int* __restrict__ col,
                            int E, int* cur, int* adj_in, int* adj_out, int n) {
    int e = blockIdx.x * blockDim.x + threadIdx.x;
    if (e >= E) return;
    int r = row[e], c = col[e];
    int p1 = atomicAdd(&cur[c], 1);
    adj_in[p1] = r;
    int p2 = atomicAdd(&cur[n + r], 1);
    adj_out[p2] = c;
}

// ---------------- gather SpMM (optional fp32 out, optional bf16 hi/lo out) --
__global__ void __launch_bounds__(256)
gather_spmm(const float* __restrict__ src, int lds,
            float* dst, int ldd,
            __nv_bfloat16* hi, __nv_bfloat16* lo, int ldh,
            const int* __restrict__ off, const int* __restrict__ adj, int N) {
    int node = blockIdx.x * blockDim.y + threadIdx.y;
    if (node >= N) return;
    int s = off[node], e = off[node + 1];
    int lane = threadIdx.x;
    float4 acc0 = make_float4(0.f, 0.f, 0.f, 0.f);
    float4 acc1 = make_float4(0.f, 0.f, 0.f, 0.f);
    int i = s;
    for (; i + 1 < e; i += 2) {
        int sr0 = __ldg(&adj[i]);
        int sr1 = __ldg(&adj[i + 1]);
        float4 v0 = *(const float4*)(src + (size_t)sr0 * lds + lane * 4);
        float4 v1 = *(const float4*)(src + (size_t)sr1 * lds + lane * 4);
        acc0.x += v0.x; acc0.y += v0.y; acc0.z += v0.z; acc0.w += v0.w;
        acc1.x += v1.x; acc1.y += v1.y; acc1.z += v1.z; acc1.w += v1.w;
    }
    if (i < e) {
        int sr = __ldg(&adj[i]);
        float4 v = *(const float4*)(src + (size_t)sr * lds + lane * 4);
        acc0.x += v.x; acc0.y += v.y; acc0.z += v.z; acc0.w += v.w;
    }
    acc0.x += acc1.x; acc0.y += acc1.y; acc0.z += acc1.z; acc0.w += acc1.w;
    if (dst)
        *(float4*)(dst + (size_t)node * ldd + lane * 4) = acc0;
    if (hi) {
        __nv_bfloat16 h0, h1, h2, h3, l0, l1, l2, l3;
        split_bf16(acc0.x, &h0, &l0); split_bf16(acc0.y, &h1, &l1);
        split_bf16(acc0.z, &h2, &l2); split_bf16(acc0.w, &h3, &l3);
        size_t o = (size_t)node * ldh + lane * 4;
        *(__nv_bfloat162*)(hi + o)     = __nv_bfloat162(h0, h1);
        *(__nv_bfloat162*)(hi + o + 2) = __nv_bfloat162(h2, h3);
        *(__nv_bfloat162*)(lo + o)     = __nv_bfloat162(l0, l1);
        *(__nv_bfloat162*)(lo + o + 2) = __nv_bfloat162(l2, l3);
    }
}

// ---------------- BN stats / apply ------------------------------------------
__global__ void colstats(const float* __restrict__ A, int lda, int N,
                         float* sum, float* ssq) {
    int c = threadIdx.x;
    float s = 0.f, q = 0.f;
    for (int r = blockIdx.x; r < N; r += gridDim.x) {
        float v = A[(size_t)r * lda + c];
        s += v;
        q += v * v;
    }
    atomicAdd(&sum[c], s);
    atomicAdd(&ssq[c], q);
}

__global__ void mkaffine(const float* sum, const float* ssq,
                         const float* g, const float* b,
                         float* scale, float* shift, int C, float invN) {
    int c = blockIdx.x * blockDim.x + threadIdx.x;
    if (c >= C) return;
    float m  = sum[c] * invN;
    float v  = fmaxf(ssq[c] * invN - m * m, 0.f);
    float sc = g[c] * rsqrtf(v + EPSV);
    scale[c] = sc;
    shift[c] = b[c] - m * sc;
}

// BN-apply on 128-col slab of 384-stride Hc + write bf16 hi/lo split
__global__ void applybn_split(float* A, int lda, int N,
                              const float* __restrict__ scale,
                              const float* __restrict__ shift,
                              __nv_bfloat16* hi, __nv_bfloat16* lo) {
    size_t total = (size_t)N * 32;      // 32 float4s per row
    size_t i  = (size_t)blockIdx.x * blockDim.x + threadIdx.x;
    size_t st = (size_t)gridDim.x * blockDim.x;
    for (; i < total; i += st) {
        int r = (int)(i >> 5), c4 = (int)(i & 31) * 4;
        float* p = A + (size_t)r * lda + c4;
        float4 v = *(float4*)p;
        v.x = fmaf(v.x, scale[c4 + 0], shift[c4 + 0]);
        v.y = fmaf(v.y, scale[c4 + 1], shift[c4 + 1]);
        v.z = fmaf(v.z, scale[c4 + 2], shift[c4 + 2]);
        v.w = fmaf(v.w, scale[c4 + 3], shift[c4 + 3]);
        *(float4*)p = v;
        __nv_bfloat16 h0, h1, h2, h3, l0, l1, l2, l3;
        split_bf16(v.x, &h0, &l0); split_bf16(v.y, &h1, &l1);
        split_bf16(v.z, &h2, &l2); split_bf16(v.w, &h3, &l3);
        size_t o = (size_t)r * lda + c4;
        *(__nv_bfloat162*)(hi + o)     = __nv_bfloat162(h0, h1);
        *(__nv_bfloat162*)(hi + o + 2) = __nv_bfloat162(h2, h3);
        *(__nv_bfloat162*)(lo + o)     = __nv_bfloat162(l0, l1);
        *(__nv_bfloat162*)(lo + o + 2) = __nv_bfloat162(l2, l3);
    }
}

// ---------------- fused BN-apply + segment add/max pooling ------------------
#define POOL_NPB 64
__global__ void __launch_bounds__(384)
pool_kernel(const float* __restrict__ Hm,
            const float* __restrict__ scale, const float* __restrict__ shift,
            const int* __restrict__ batch, int N,
            float* Hadd, float* Hmax, float* cnt) {
    __shared__ int sb[POOL_NPB];
    int c  = threadIdx.x;
    int n0 = blockIdx.x * POOL_NPB;
    int nEnd = min(n0 + POOL_NPB, N);
    if (c < POOL_NPB && n0 + c < N) sb[c] = batch[n0 + c];
    __syncthreads();

    float sc = scale[c], sh = shift[c];
    float accA = 0.f, accM = -INFINITY, accC = 0.f;
    int curg = -1;
    for (int n = n0; n < nEnd; n++) {
        int g = sb[n - n0];
        if (g != curg) {
            if (curg >= 0) {
                atomicAdd(&Hadd[(size_t)curg * MM + c], accA);
                atomicMaxF(&Hmax[(size_t)curg * MM + c], accM);
                if (c == 0) atomicAdd(&cnt[curg], accC);
            }
            accA = 0.f; accM = -INFINITY; accC = 0.f; curg = g;
        }
        float v = fmaf(Hm[(size_t)n * MM + c], sc, sh);
        accA += v;
        accM = fmaxf(accM, v);
        accC += 1.f;
    }
    if (curg >= 0) {
        atomicAdd(&Hadd[(size_t)curg * MM + c], accA);
        atomicMaxF(&Hmax[(size_t)curg * MM + c], accM);
        if (c == 0) atomicAdd(&cnt[curg], accC);
    }
}

// ---------------- BN over graphs (writes TRANSPOSED h0: [col][graph]) -------
__global__ void bn_graphs(const float* __restrict__ Hadd,
                          const float* __restrict__ Hmax,
                          const float* __restrict__ cnt,
                          const float* __restrict__ g,
                          const float* __restrict__ b,
                          float* __restrict__ h0) {
    int col = blockIdx.x;
    int t   = threadIdx.x;
    float v;
    if (col < MM) {
        v = Hadd[(size_t)t * MM + col] / fmaxf(cnt[t], 1.f);
    } else if (col < 2 * MM) {
        v = Hadd[(size_t)t * MM + (col - MM)];
    } else {
        v = Hmax[(size_t)t * MM + (col - 2 * MM)];
        if (!isfinite(v)) v = 0.f;
    }
    __shared__ float s1[128], s2[128];
    s1[t] = v; s2[t] = v * v;
    __syncthreads();
    for (int o = 64; o > 0; o >>= 1) {
        if (t < o) { s1[t] += s1[t + o]; s2[t] += s2[t + o]; }
        __syncthreads();
    }
    float m   = s1[0] * (1.f / 128.f);
    float var = fmaxf(s2[0] * (1.f / 128.f) - m * m, 0.f);
    h0[(size_t)col * NG + t] = (v - m) * rsqrtf(var + EPSV) * g[col] + b[col];
}

// ---------------- tiny MLP layers (transposed [feat][graph] layout) ---------
__global__ void mlp_layer_t(const float* __restrict__ X,   // [K][NG]
                            const float* __restrict__ W, int ldw,
                            const float* __restrict__ bias,
                            float* __restrict__ Y,         // [O][NG]
                            int K, int doRelu) {
    int o = blockIdx.x;
    int gI = threadIdx.x;
    const float* w = W + (size_t)o * ldw;
    float acc = 0.f;
    for (int k = 0; k < K; k++)
        acc = fmaf(X[(size_t)k * NG + gI], __ldg(&w[k]), acc);
    acc += bias[o];
    if (doRelu) acc = fmaxf(acc, 0.f);
    Y[(size_t)o * NG + gI] = acc;
}

__global__ void head_kernel(const float* __restrict__ h2,   // [MM][NG]
                            const float* __restrict__ w3,
                            const float* __restrict__ b3,
                            float* __restrict__ out) {
    int gI = threadIdx.x;
    float l0 = b3[0], l1 = b3[1];
    for (int k = 0; k < MM; k++) {
        float x = h2[(size_t)k * NG + gI];
        l0 = fmaf(x, __ldg(&w3[k]), l0);
        l1 = fmaf(x, __ldg(&w3[MM + k]), l1);
    }
    float mx  = fmaxf(l0, l1);
    float lse = mx + logf(expf(l0 - mx) + expf(l1 - mx));
    out[gI * 2 + 0] = l0 - lse;
    out[gI * 2 + 1] = l1 - lse;
}

// ---------------- launcher ---------------------------------------------------
extern "C" void kernel_launch(void* const* d_in, const int* in_sizes, int n_in,
                              void* d_out, int out_size) {
    const float* x       = (const float*)d_in[0];
    const int*   eidx    = (const int*)d_in[1];
    const int*   batch   = (const int*)d_in[2];
    const float* w_rel   = (const float*)d_in[4];
    const float* b_rel   = (const float*)d_in[5];
    const float* w_root  = (const float*)d_in[6];
    const float* norm0_g = (const float*)d_in[7];
    const float* norm0_b = (const float*)d_in[8];
    const float* lin_w   = (const float*)d_in[9];
    const float* lin_b   = (const float*)d_in[10];
    const float* bnh_g   = (const float*)d_in[11];
    const float* bnh_b   = (const float*)d_in[12];
    const float* bno_g   = (const float*)d_in[13];
    const float* bno_b   = (const float*)d_in[14];
    const float* w1      = (const float*)d_in[15];
    const float* b1      = (const float*)d_in[16];
    const float* w2      = (const float*)d_in[17];
    const float* b2      = (const float*)d_in[18];
    const float* w3      = (const float*)d_in[19];
    const float* b3      = (const float*)d_in[20];
    float* out = (float*)d_out;

    const int* row = eidx;
    const int* col = eidx + NE;

    float *Hc, *Hm, *Hadd, *Hmax, *cnt;
    float *sum0, *ssq0, *scale0, *shift0, *sumH, *ssqH, *scaleH, *shiftH;
    float *h0, *h1, *h2;
    int *deg, *off_in, *off_out, *cur, *adj_in, *adj_out;
    __nv_bfloat16 *wrt_hi, *wrt_lo, *wrl_hi, *wrl_lo, *wl_hi, *wl_lo;
    __nv_bfloat16 *abuf_hi, *abuf_lo, *Hchi, *Hclo;
    cudaGetSymbolAddress((void**)&Hc,     g_Hc);
    cudaGetSymbolAddress((void**)&Hm,     g_Hm);
    cudaGetSymbolAddress((void**)&Hadd,   g_Hadd);
    cudaGetSymbolAddress((void**)&Hmax,   g_Hmax);
    cudaGetSymbolAddress((void**)&cnt,    g_cnt);
    cudaGetSymbolAddress((void**)&sum0,   g_sum0);
    cudaGetSymbolAddress((void**)&ssq0,   g_ssq0);
    cudaGetSymbolAddress((void**)&scale0, g_scale0);
    cudaGetSymbolAddress((void**)&shift0, g_shift0);
    cudaGetSymbolAddress((void**)&sumH,   g_sumH);
    cudaGetSymbolAddress((void**)&ssqH,   g_ssqH);
    cudaGetSymbolAddress((void**)&scaleH, g_scaleH);
    cudaGetSymbolAddress((void**)&shiftH, g_shiftH);
    cudaGetSymbolAddress((void**)&h0,     g_h0);
    cudaGetSymbolAddress((void**)&h1,     g_h1);
    cudaGetSymbolAddress((void**)&h2,     g_h2);
    cudaGetSymbolAddress((void**)&deg,     g_deg);
    cudaGetSymbolAddress((void**)&off_in,  g_off_in);
    cudaGetSymbolAddress((void**)&off_out, g_off_out);
    cudaGetSymbolAddress((void**)&cur,     g_cur);
    cudaGetSymbolAddress((void**)&adj_in,  g_adj_in);
    cudaGetSymbolAddress((void**)&adj_out, g_adj_out);
    cudaGetSymbolAddress((void**)&wrt_hi,  g_wrt_hi);
    cudaGetSymbolAddress((void**)&wrt_lo,  g_wrt_lo);
    cudaGetSymbolAddress((void**)&wrl_hi,  g_wrl_hi);
    cudaGetSymbolAddress((void**)&wrl_lo,  g_wrl_lo);
    cudaGetSymbolAddress((void**)&wl_hi,   g_wl_hi);
    cudaGetSymbolAddress((void**)&wl_lo,   g_wl_lo);
    cudaGetSymbolAddress((void**)&abuf_hi, g_abuf_hi);
    cudaGetSymbolAddress((void**)&abuf_lo, g_abuf_lo);
    cudaGetSymbolAddress((void**)&Hchi,    g_Hchi);
    cudaGetSymbolAddress((void**)&Hclo,    g_Hclo);

    cudaFuncSetAttribute(hmma_gemm, cudaFuncAttributeMaxDynamicSharedMemorySize, HM_SMEM);

    int ggrid = (NN + 127) / 128;        // 391 row blocks
    dim3 gblk(32, 8);
    int ggrid_n = (NN + 7) / 8;

    // #1..#3
    fill_i<<<256, 256>>>(deg, (size_t)2 * NN, 0);
    prep_w<<<(384 * 384 + 255) / 256, 256>>>(w_root, w_rel, lin_w);
    split_arr<<<1024, 256>>>(x, abuf_hi, abuf_lo, (size_t)NN * CIN / 4);

    // #4 (ncu-profiled): Hc[:,0:128] = x @ w_root^T + b_rel
    hmma_gemm<<<dim3(ggrid, 1), 256, HM_SMEM>>>(
        abuf_hi, abuf_lo, CIN, wrt_hi, wrt_lo, 128, b_rel, Hc, MM, NN, 128, 0, 0);

    // init small scratch (one launch)
    init_misc<<<(NG * MM + 255) / 256, 256>>>(Hadd, Hmax, cnt, sum0, ssq0, sumH, ssqH);

    // CSR build + GraphConv gather (writes bf16 hi/lo only; reuses abuf)
    count_deg<<<(NE + 255) / 256, 256>>>(row, col, NE, deg, deg + NN);
    exscan2c<<<1, 1024>>>(deg, off_in, deg + NN, off_out, cur, NN);
    build_lists<<<(NE + 255) / 256, 256>>>(row, col, NE, cur, adj_in, adj_out, NN);
    gather_spmm<<<ggrid_n, gblk>>>(x, CIN, nullptr, 0, abuf_hi, abuf_lo, CIN,
                                   off_in, adj_in, NN);

    // Hc[:,0:128] += neigh @ w_rel^T
    hmma_gemm<<<dim3(ggrid, 1), 256, HM_SMEM>>>(
        abuf_hi, abuf_lo, CIN, wrl_hi, wrl_lo, 128, nullptr, Hc, MM, NN, 128, 0, 1);

    // BN0 stats + apply in place (+ bf16 split of X block)
    colstats<<<512, PROJ>>>(Hc, MM, NN, sum0, ssq0);
    mkaffine<<<1, PROJ>>>(sum0, ssq0, norm0_g, norm0_b, scale0, shift0, PROJ, 1.f / NN);
    applybn_split<<<2048, 256>>>(Hc, MM, NN, scale0, shift0, Hchi, Hclo);

    // k-hop diffusion: H1 (fp32 + split), H2 (split only)
    gather_spmm<<<ggrid_n, gblk>>>(Hc, MM, Hc + PROJ, MM, Hchi + PROJ, Hclo + PROJ, MM,
                                   off_out, adj_out, NN);
    gather_spmm<<<ggrid_n, gblk>>>(Hc + PROJ, MM, nullptr, 0, Hchi + 2 * PROJ, Hclo + 2 * PROJ, MM,
                                   off_out, adj_out, NN);

    // masked lin: 3 col-blocks, K = 128*(y+1)
    hmma_gemm<<<dim3(ggrid, 3), 256, HM_SMEM>>>(
        Hchi, Hclo, MM, wl_hi, wl_lo, MM, lin_b, Hm, MM, NN, 128, 1, 0);

    // BN over nodes (stats only; affine fused into pooling)
    colstats<<<512, MM>>>(Hm, MM, NN, sumH, ssqH);
    mkaffine<<<2, 256>>>(sumH, ssqH, bnh_g, bnh_b, scaleH, shiftH, MM, 1.f / NN);

    // pooling
    pool_kernel<<<(NN + POOL_NPB - 1) / POOL_NPB, 384>>>(
        Hm, scaleH, shiftH, batch, NN, Hadd, Hmax, cnt);

    // graph BN (transposed h0) + funnel MLP + log_softmax
    bn_graphs<<<M3, 128>>>(Hadd, Hmax, cnt, bno_g, bno_b, h0);
    mlp_layer_t<<<768, 128>>>(h0, w1, M3, b1, h1, M3, 1);
    mlp_layer_t<<<MM, 128>>>(h1, w2, 768, b2, h2, 768, 1);
    head_kernel<<<1, 128>>>(h2, w3, b3, out);
}